// round 8
// baseline (speedup 1.0000x reference)
#include <cuda_runtime.h>
#include <cuda_bf16.h>
#include <mma.h>
#include <math.h>
#include <stdint.h>

using namespace nvcuda;

#define NTOK 8192
#define EDIM 512
#define SEQ  2048
#define NB   4
#define HEADS 8
#define HD   64
#define FFDIM 2048
#define NLAYER 2

typedef __nv_bfloat16 bf16;
typedef __nv_bfloat162 bf162;

// ---------------- scratch (device globals; no allocation) ----------------
__device__ float g_h32[NTOK * EDIM];
__device__ float g_p32[NTOK * EDIM];
__device__ bf16 g_hh[NTOK * EDIM], g_hl[NTOK * EDIM];
__device__ bf16 g_qh[NTOK * EDIM], g_ql[NTOK * EDIM];
__device__ bf16 g_kh[NTOK * EDIM], g_kl[NTOK * EDIM];
__device__ bf16 g_vh[NTOK * EDIM], g_vl[NTOK * EDIM];
__device__ bf16 g_ah[NTOK * EDIM], g_al[NTOK * EDIM];
__device__ bf16 g_fh[NTOK * FFDIM], g_fl[NTOK * FFDIM];
__device__ bf16 g_wqh[NLAYER * EDIM * EDIM], g_wql[NLAYER * EDIM * EDIM];
__device__ bf16 g_wkh[NLAYER * EDIM * EDIM], g_wkl[NLAYER * EDIM * EDIM];
__device__ bf16 g_wvh[NLAYER * EDIM * EDIM], g_wvl[NLAYER * EDIM * EDIM];
__device__ bf16 g_woh[NLAYER * EDIM * EDIM], g_wol[NLAYER * EDIM * EDIM];
__device__ bf16 g_w1h[NLAYER * EDIM * FFDIM], g_w1l[NLAYER * EDIM * FFDIM];
__device__ bf16 g_w2h[NLAYER * FFDIM * EDIM], g_w2l[NLAYER * FFDIM * EDIM];

__device__ __forceinline__ void split1(float x, bf16& h, bf16& l) {
    h = __float2bfloat16(x);
    l = __float2bfloat16(x - __bfloat162float(h));
}

__device__ __forceinline__ void cp_async16(void* smem, const void* gmem) {
    unsigned int s = (unsigned int)__cvta_generic_to_shared(smem);
    asm volatile("cp.async.cg.shared.global [%0], [%1], 16;\n" :: "r"(s), "l"(gmem));
}
__device__ __forceinline__ void cp_commit() {
    asm volatile("cp.async.commit_group;\n");
}
template <int N>
__device__ __forceinline__ void cp_wait() {
    asm volatile("cp.async.wait_group %0;\n" :: "n"(N));
}

// ---------------- weight pre-split ----------------
__global__ void split_kernel(const float* __restrict__ src, bf16* __restrict__ hi,
                             bf16* __restrict__ lo) {
    int i = (blockIdx.x * 256 + threadIdx.x) * 4;
    float4 v = *(const float4*)(src + i);
    bf16 h0, l0, h1, l1, h2, l2, h3, l3;
    split1(v.x, h0, l0); split1(v.y, h1, l1);
    split1(v.z, h2, l2); split1(v.w, h3, l3);
    *(bf162*)(hi + i)     = bf162(h0, h1);
    *(bf162*)(hi + i + 2) = bf162(h2, h3);
    *(bf162*)(lo + i)     = bf162(l0, l1);
    *(bf162*)(lo + i + 2) = bf162(l2, l3);
}

// ---------------- embedding + positional (fp32 + split) ----------------
__global__ void embed_kernel(const int* __restrict__ x,
                             const float* __restrict__ emb,
                             const float* __restrict__ pos,
                             float* __restrict__ h,
                             bf16* __restrict__ hh, bf16* __restrict__ hl) {
    int idx = blockIdx.x * blockDim.x + threadIdx.x;
    int n = idx >> 9;
    int e = idx & 511;
    int tok = x[n] + 1;
    int s = n & (SEQ - 1);
    float v = emb[tok * EDIM + e] + pos[s * EDIM + e];
    h[idx] = v;
    bf16 hv, lv;
    split1(v, hv, lv);
    hh[idx] = hv;
    hl[idx] = lv;
}

// ---------------- bf16x3 tensor-core GEMM ----------------
#define BM 128
#define BN 128
#define BK 32
#define SA_STR 56
#define SB_STR 136
#define EPI_STR 68
#define ABUFH (BM * SA_STR)
#define STG_A (2 * ABUFH)
#define BBUFH (BK * SB_STR)
#define STG_B (2 * BBUFH)
#define STG_ELEMS (STG_A + STG_B)
#define NSTAGE 2
#define GEMM_SMEM (NSTAGE * STG_ELEMS * 2)   // 92160 bytes

__device__ __forceinline__
void gemm_load_stage(const bf16* Ah, const bf16* Al, const bf16* Wh, const bf16* Wl,
                     int K, int M, int rowBase, int colBase, int k0,
                     bf16* st, int tid) {
    bf16* sAh = st;
    bf16* sAl = st + ABUFH;
    bf16* sBh = st + STG_A;
    bf16* sBl = st + STG_A + BBUFH;
    #pragma unroll
    for (int i = 0; i < 4; i++) {
        int f = tid + i * 128;
        int r = f >> 2, c = (f & 3) * 8;
        cp_async16(&sAh[r * SA_STR + c], Ah + (size_t)(rowBase + r) * K + k0 + c);
        cp_async16(&sAl[r * SA_STR + c], Al + (size_t)(rowBase + r) * K + k0 + c);
        int rB = f >> 4, cB = (f & 15) * 8;
        cp_async16(&sBh[rB * SB_STR + cB], Wh + (size_t)(k0 + rB) * M + colBase + cB);
        cp_async16(&sBl[rB * SB_STR + cB], Wl + (size_t)(k0 + rB) * M + colBase + cB);
    }
}

// MODE: 0 = fp32 out, 1 = split out, 2 = split + relu out
template <int MODE>
__device__ __forceinline__
void gemm_body(const bf16* Ah, const bf16* Al, const bf16* Wh, const bf16* Wl,
               const float* __restrict__ bias, float* C, bf16* Chi, bf16* Clo,
               int K, int M, int rowBase, int colBase, char* dynsmem) {
    bf16* base = (bf16*)dynsmem;
    int tid = threadIdx.x;
    int lane = tid & 31;
    int wid = tid >> 5;
    int wm = wid & 1;
    int wn = wid >> 1;
    int nk = K / BK;

    wmma::fragment<wmma::accumulator, 16, 16, 16, float> acc[4][4];
    #pragma unroll
    for (int i = 0; i < 4; i++)
        #pragma unroll
        for (int j = 0; j < 4; j++)
            wmma::fill_fragment(acc[i][j], 0.0f);

    gemm_load_stage(Ah, Al, Wh, Wl, K, M, rowBase, colBase, 0, base, tid);
    cp_commit();
    gemm_load_stage(Ah, Al, Wh, Wl, K, M, rowBase, colBase, BK, base + STG_ELEMS, tid);
    cp_commit();

    for (int kc = 0; kc < nk; kc++) {
        cp_wait<1>();
        __syncthreads();

        bf16* st = base + (kc & 1) * STG_ELEMS;
        bf16* sAh = st;
        bf16* sAl = st + ABUFH;
        bf16* sBh = st + STG_A;
        bf16* sBl = st + STG_A + BBUFH;
        #pragma unroll
        for (int ks = 0; ks < BK; ks += 16) {
            wmma::fragment<wmma::matrix_a, 16, 16, 16, bf16, wmma::row_major> ah[4], al[4];
            wmma::fragment<wmma::matrix_b, 16, 16, 16, bf16, wmma::row_major> bh[4], bl[4];
            #pragma unroll
            for (int i = 0; i < 4; i++)
                wmma::load_matrix_sync(ah[i], &sAh[(wm * 64 + i * 16) * SA_STR + ks], SA_STR);
            #pragma unroll
            for (int j = 0; j < 4; j++)
                wmma::load_matrix_sync(bh[j], &sBh[ks * SB_STR + wn * 64 + j * 16], SB_STR);
            #pragma unroll
            for (int i = 0; i < 4; i++)
                #pragma unroll
                for (int j = 0; j < 4; j++)
                    wmma::mma_sync(acc[i][j], ah[i], bh[j], acc[i][j]);
            #pragma unroll
            for (int j = 0; j < 4; j++)
                wmma::load_matrix_sync(bl[j], &sBl[ks * SB_STR + wn * 64 + j * 16], SB_STR);
            #pragma unroll
            for (int i = 0; i < 4; i++)
                #pragma unroll
                for (int j = 0; j < 4; j++)
                    wmma::mma_sync(acc[i][j], ah[i], bl[j], acc[i][j]);
            #pragma unroll
            for (int i = 0; i < 4; i++)
                wmma::load_matrix_sync(al[i], &sAl[(wm * 64 + i * 16) * SA_STR + ks], SA_STR);
            #pragma unroll
            for (int i = 0; i < 4; i++)
                #pragma unroll
                for (int j = 0; j < 4; j++)
                    wmma::mma_sync(acc[i][j], al[i], bh[j], acc[i][j]);
        }
        __syncthreads();

        if (kc + 2 < nk)
            gemm_load_stage(Ah, Al, Wh, Wl, K, M, rowBase, colBase, (kc + 2) * BK,
                            base + (kc & 1) * STG_ELEMS, tid);
        cp_commit();
    }

    cp_wait<0>();
    __syncthreads();

    float* stg = (float*)dynsmem + wid * (64 * EPI_STR);
    #pragma unroll
    for (int i = 0; i < 4; i++)
        #pragma unroll
        for (int j = 0; j < 4; j++)
            wmma::store_matrix_sync(stg + i * 16 * EPI_STR + j * 16, acc[i][j],
                                    EPI_STR, wmma::mem_row_major);
    __syncwarp();

    int rowW = rowBase + wm * 64;
    int colW = colBase + wn * 64;
    #pragma unroll
    for (int it = 0; it < 32; it++) {
        int f = it * 32 + lane;
        int r = f >> 4;
        int c4 = (f & 15) << 2;
        float4 v = *(float4*)(stg + r * EPI_STR + c4);
        float4 bb = *(const float4*)(bias + colW + c4);
        v.x += bb.x; v.y += bb.y; v.z += bb.z; v.w += bb.w;
        if (MODE == 2) {
            v.x = fmaxf(v.x, 0.f); v.y = fmaxf(v.y, 0.f);
            v.z = fmaxf(v.z, 0.f); v.w = fmaxf(v.w, 0.f);
        }
        if (MODE == 0) {
            *(float4*)(C + (size_t)(rowW + r) * M + colW + c4) = v;
        } else {
            bf16 h0, l0, h1, l1, h2, l2, h3, l3;
            split1(v.x, h0, l0); split1(v.y, h1, l1);
            split1(v.z, h2, l2); split1(v.w, h3, l3);
            size_t off = (size_t)(rowW + r) * M + colW + c4;
            *(bf162*)(Chi + off)     = bf162(h0, h1);
            *(bf162*)(Chi + off + 2) = bf162(h2, h3);
            *(bf162*)(Clo + off)     = bf162(l0, l1);
            *(bf162*)(Clo + off + 2) = bf162(l2, l3);
        }
    }
}

template <int MODE>
__global__ __launch_bounds__(128, 2)
void gemm_tc_kernel(const bf16* Ah, const bf16* Al, const bf16* Wh, const bf16* Wl,
                    const float* __restrict__ bias, float* C, bf16* Chi, bf16* Clo,
                    int K, int M) {
    extern __shared__ char dynsmem[];
    gemm_body<MODE>(Ah, Al, Wh, Wl, bias, C, Chi, Clo, K, M,
                    blockIdx.y * BM, blockIdx.x * BN, dynsmem);
}

__global__ __launch_bounds__(128, 2)
void gemm_qkv_kernel(const bf16* Ah, const bf16* Al,
                     const bf16* Wqh, const bf16* Wql, const bf16* Wkh, const bf16* Wkl,
                     const bf16* Wvh, const bf16* Wvl,
                     const float* bq, const float* bk, const float* bv,
                     bf16* qh, bf16* ql, bf16* kh, bf16* kl, bf16* vh, bf16* vl) {
    extern __shared__ char dynsmem[];
    const bf16 *Wh, *Wl;
    const float* bias;
    bf16 *Chi, *Clo;
    if (blockIdx.z == 0)      { Wh = Wqh; Wl = Wql; bias = bq; Chi = qh; Clo = ql; }
    else if (blockIdx.z == 1) { Wh = Wkh; Wl = Wkl; bias = bk; Chi = kh; Clo = kl; }
    else                      { Wh = Wvh; Wl = Wvl; bias = bv; Chi = vh; Clo = vl; }
    gemm_body<1>(Ah, Al, Wh, Wl, bias, nullptr, Chi, Clo, EDIM, EDIM,
                 blockIdx.y * BM, blockIdx.x * BN, dynsmem);
}

// ---------------- tensor-core flash attention: 128-query tile ----------
// 256 threads / 8 warps; warp tile 32x32 on the 128x64 S / O tiles.
#define QT 128
#define KSTR 72
#define SSTR 68
// element offsets in the bf16 region
#define AQH 0
#define AQL (QT * KSTR)                       // 9216
#define AKH (2 * QT * KSTR)                   // 18432
#define AKL (AKH + 64 * KSTR)                 // 23040
#define AVH (AKH + 2 * 64 * KSTR)             // 27648
#define AVL (AKH + 3 * 64 * KSTR)             // 32256
#define APH (AKH + 4 * 64 * KSTR)             // 36864
#define APL (APH + QT * KSTR)                 // 46080
#define SF_OFF ((APL + QT * KSTR) * 2)        // byte offset 110592
#define ATTN_SMEM (SF_OFF + QT * SSTR * 4)    // 145408 bytes

__device__ __forceinline__
void attn_load_kv(const bf16* gh, const bf16* gl, bf16* sb, int offH, int offL,
                  size_t rowG, int colB, int tid) {
    #pragma unroll
    for (int i = 0; i < 2; i++) {
        int f = tid + i * 256;
        int r = f >> 3, c = (f & 7) * 8;
        cp_async16(&sb[offH + r * KSTR + c], gh + (rowG + r) * EDIM + colB + c);
        cp_async16(&sb[offL + r * KSTR + c], gl + (rowG + r) * EDIM + colB + c);
    }
}

__global__ __launch_bounds__(256, 1)
void attn_tc_kernel(const bf16* __restrict__ qh, const bf16* __restrict__ ql,
                    const bf16* __restrict__ kh, const bf16* __restrict__ kl,
                    const bf16* __restrict__ vh, const bf16* __restrict__ vl,
                    const int* __restrict__ mask,
                    bf16* __restrict__ oh, bf16* __restrict__ ol) {
    extern __shared__ char smraw[];
    bf16* sb = (bf16*)smraw;
    float* Sf = (float*)(smraw + SF_OFF);

    int tid = threadIdx.x;
    int wid = tid >> 5;
    int wr = (wid & 3) * 32;          // warp row band (queries / output rows)
    int wc = (wid >> 2) * 32;         // warp col band (keys for S; d for O)
    int b  = blockIdx.y >> 3;
    int hh = blockIdx.y & 7;
    int q0 = blockIdx.x * QT;
    int colB = hh * HD;
    size_t qrow = (size_t)(b * SEQ + q0);
    size_t krow = (size_t)(b * SEQ);

    // stage Q (128 rows, scaled by 1/8)
    {
        bf162 sc = __float2bfloat162_rn(0.125f);
        #pragma unroll
        for (int i = 0; i < 4; i++) {
            int f = tid + i * 256;
            int r = f >> 3, c = (f & 7) * 8;
            uint4 uh = *(const uint4*)(qh + (qrow + r) * EDIM + colB + c);
            uint4 ulo = *(const uint4*)(ql + (qrow + r) * EDIM + colB + c);
            bf162* ph = (bf162*)&uh;
            bf162* pl = (bf162*)&ulo;
            #pragma unroll
            for (int j = 0; j < 4; j++) { ph[j] = __hmul2(ph[j], sc); pl[j] = __hmul2(pl[j], sc); }
            *(uint4*)&sb[AQH + r * KSTR + c] = uh;
            *(uint4*)&sb[AQL + r * KSTR + c] = ulo;
        }
    }

    int rr = tid >> 1;                // 0..127 query row
    int pp = tid & 1;                 // 32-col half
    float o_acc[32];
    #pragma unroll
    for (int i = 0; i < 32; i++) o_acc[i] = 0.f;
    float mrun = -1e30f, lrun = 0.f;

    attn_load_kv(kh, kl, sb, AKH, AKL, krow, colB, tid);
    attn_load_kv(vh, vl, sb, AVH, AVL, krow, colB, tid);
    cp_commit();

    for (int kb = 0; kb < SEQ / 64; kb++) {
        cp_wait<0>();
        __syncthreads();

        // S = Q @ K^T (128x64x64)
        {
            wmma::fragment<wmma::matrix_a, 16, 16, 16, bf16, wmma::row_major> qa_h[2], qa_l[2];
            wmma::fragment<wmma::matrix_b, 16, 16, 16, bf16, wmma::col_major> kb_h[2], kb_l[2];
            wmma::fragment<wmma::accumulator, 16, 16, 16, float> sacc[2][2];
            #pragma unroll
            for (int i = 0; i < 2; i++)
                #pragma unroll
                for (int j = 0; j < 2; j++)
                    wmma::fill_fragment(sacc[i][j], 0.f);
            #pragma unroll
            for (int kk = 0; kk < 4; kk++) {
                #pragma unroll
                for (int i = 0; i < 2; i++) {
                    wmma::load_matrix_sync(qa_h[i], &sb[AQH + (wr + i * 16) * KSTR + kk * 16], KSTR);
                    wmma::load_matrix_sync(qa_l[i], &sb[AQL + (wr + i * 16) * KSTR + kk * 16], KSTR);
                }
                #pragma unroll
                for (int j = 0; j < 2; j++) {
                    wmma::load_matrix_sync(kb_h[j], &sb[AKH + (wc + j * 16) * KSTR + kk * 16], KSTR);
                    wmma::load_matrix_sync(kb_l[j], &sb[AKL + (wc + j * 16) * KSTR + kk * 16], KSTR);
                }
                #pragma unroll
                for (int i = 0; i < 2; i++)
                    #pragma unroll
                    for (int j = 0; j < 2; j++) {
                        wmma::mma_sync(sacc[i][j], qa_h[i], kb_h[j], sacc[i][j]);
                        wmma::mma_sync(sacc[i][j], qa_h[i], kb_l[j], sacc[i][j]);
                        wmma::mma_sync(sacc[i][j], qa_l[i], kb_h[j], sacc[i][j]);
                    }
            }
            #pragma unroll
            for (int i = 0; i < 2; i++)
                #pragma unroll
                for (int j = 0; j < 2; j++)
                    wmma::store_matrix_sync(&Sf[(wr + i * 16) * SSTR + wc + j * 16],
                                            sacc[i][j], SSTR, wmma::mem_row_major);
        }
        __syncthreads();

        if (kb + 1 < SEQ / 64)
            attn_load_kv(kh, kl, sb, AKH, AKL, krow + (kb + 1) * 64, colB, tid);
        cp_commit();

        // softmax: 2 threads/row, 32 cols each
        {
            const float* srow = &Sf[rr * SSTR + pp * 32];
            const int4* mrow = (const int4*)(mask + b * SEQ + kb * 64 + pp * 32);
            float s[32];
            #pragma unroll
            for (int i = 0; i < 8; i++) {
                float4 sv = *(const float4*)(srow + i * 4);
                int4 mk = mrow[i];
                s[4 * i + 0] = mk.x ? sv.x : -1e20f;
                s[4 * i + 1] = mk.y ? sv.y : -1e20f;
                s[4 * i + 2] = mk.z ? sv.z : -1e20f;
                s[4 * i + 3] = mk.w ? sv.w : -1e20f;
            }
            float mloc = s[0];
            #pragma unroll
            for (int i = 1; i < 32; i++) mloc = fmaxf(mloc, s[i]);
            mloc = fmaxf(mloc, __shfl_xor_sync(0xffffffffu, mloc, 1));
            float mnew = fmaxf(mrun, mloc);
            float corr = __expf(mrun - mnew);
            mrun = mnew;
            float psum = 0.f;
            bf162* ph = (bf162*)&sb[APH + rr * KSTR + pp * 32];
            bf162* pl = (bf162*)&sb[APL + rr * KSTR + pp * 32];
            #pragma unroll
            for (int i = 0; i < 16; i++) {
                float p0 = __expf(s[2 * i] - mnew);
                float p1 = __expf(s[2 * i + 1] - mnew);
                psum += p0 + p1;
                bf16 h0, l0, h1, l1;
                split1(p0, h0, l0); split1(p1, h1, l1);
                ph[i] = bf162(h0, h1);
                pl[i] = bf162(l0, l1);
            }
            psum += __shfl_xor_sync(0xffffffffu, psum, 1);
            lrun = lrun * corr + psum;
            #pragma unroll
            for (int i = 0; i < 32; i++) o_acc[i] *= corr;
        }
        __syncthreads();

        // Opart = P @ V (128x64x64)
        {
            wmma::fragment<wmma::matrix_a, 16, 16, 16, bf16, wmma::row_major> pa_h[2], pa_l[2];
            wmma::fragment<wmma::matrix_b, 16, 16, 16, bf16, wmma::row_major> vb_h[2], vb_l[2];
            wmma::fragment<wmma::accumulator, 16, 16, 16, float> oacc[2][2];
            #pragma unroll
            for (int i = 0; i < 2; i++)
                #pragma unroll
                for (int j = 0; j < 2; j++)
                    wmma::fill_fragment(oacc[i][j], 0.f);
            #pragma unroll
            for (int kk = 0; kk < 4; kk++) {
                #pragma unroll
                for (int i = 0; i < 2; i++) {
                    wmma::load_matrix_sync(pa_h[i], &sb[APH + (wr + i * 16) * KSTR + kk * 16], KSTR);
                    wmma::load_matrix_sync(pa_l[i], &sb[APL + (wr + i * 16) * KSTR + kk * 16], KSTR);
                }
                #pragma unroll
                for (int j = 0; j < 2; j++) {
                    wmma::load_matrix_sync(vb_h[j], &sb[AVH + (kk * 16) * KSTR + wc + j * 16], KSTR);
                    wmma::load_matrix_sync(vb_l[j], &sb[AVL + (kk * 16) * KSTR + wc + j * 16], KSTR);
                }
                #pragma unroll
                for (int i = 0; i < 2; i++)
                    #pragma unroll
                    for (int j = 0; j < 2; j++) {
                        wmma::mma_sync(oacc[i][j], pa_h[i], vb_h[j], oacc[i][j]);
                        wmma::mma_sync(oacc[i][j], pa_h[i], vb_l[j], oacc[i][j]);
                        wmma::mma_sync(oacc[i][j], pa_l[i], vb_h[j], oacc[i][j]);
                    }
            }
            #pragma unroll
            for (int i = 0; i < 2; i++)
                #pragma unroll
                for (int j = 0; j < 2; j++)
                    wmma::store_matrix_sync(&Sf[(wr + i * 16) * SSTR + wc + j * 16],
                                            oacc[i][j], SSTR, wmma::mem_row_major);
        }
        __syncthreads();

        if (kb + 1 < SEQ / 64)
            attn_load_kv(vh, vl, sb, AVH, AVL, krow + (kb + 1) * 64, colB, tid);
        cp_commit();

        // accumulate O part
        {
            const float* orow = &Sf[rr * SSTR + pp * 32];
            #pragma unroll
            for (int i = 0; i < 8; i++) {
                float4 op = *(const float4*)(orow + i * 4);
                o_acc[4 * i + 0] += op.x;
                o_acc[4 * i + 1] += op.y;
                o_acc[4 * i + 2] += op.z;
                o_acc[4 * i + 3] += op.w;
            }
        }
    }

    float inv = 1.f / lrun;
    size_t obase = (qrow + rr) * EDIM + colB + pp * 32;
    #pragma unroll
    for (int i = 0; i < 16; i++) {
        float v0 = o_acc[2 * i] * inv;
        float v1 = o_acc[2 * i + 1] * inv;
        bf16 h0, l0, h1, l1;
        split1(v0, h0, l0); split1(v1, h1, l1);
        *(bf162*)(oh + obase + 2 * i) = bf162(h0, h1);
        *(bf162*)(ol + obase + 2 * i) = bf162(l0, l1);
    }
}

// ---------------- residual + LayerNorm (fp32 out + optional split) ------
template <bool SPLIT>
__global__ __launch_bounds__(128)
void ln_kernel(const float* __restrict__ A, const float* __restrict__ R,
               const float* __restrict__ g, const float* __restrict__ be,
               float* __restrict__ out, bf16* __restrict__ ohi, bf16* __restrict__ olo) {
    __shared__ float red[4];
    int n = blockIdx.x;
    int t = threadIdx.x;
    float4 a = ((const float4*)(A + (size_t)n * EDIM))[t];
    float4 r = ((const float4*)(R + (size_t)n * EDIM))[t];
    float v[4] = {a.x + r.x, a.y + r.y, a.z + r.z, a.w + r.w};

    float s = v[0] + v[1] + v[2] + v[3];
    #pragma unroll
    for (int o = 16; o; o >>= 1) s += __shfl_xor_sync(0xffffffffu, s, o);
    if ((t & 31) == 0) red[t >> 5] = s;
    __syncthreads();
    float mu = (red[0] + red[1] + red[2] + red[3]) * (1.f / EDIM);
    __syncthreads();

    v[0] -= mu; v[1] -= mu; v[2] -= mu; v[3] -= mu;
    float sq = v[0] * v[0] + v[1] * v[1] + v[2] * v[2] + v[3] * v[3];
    #pragma unroll
    for (int o = 16; o; o >>= 1) sq += __shfl_xor_sync(0xffffffffu, sq, o);
    if ((t & 31) == 0) red[t >> 5] = sq;
    __syncthreads();
    float var = (red[0] + red[1] + red[2] + red[3]) * (1.f / EDIM);
    float rs = rsqrtf(var + 1e-6f);

    float4 gg = ((const float4*)g)[t];
    float4 bb = ((const float4*)be)[t];
    float o0 = v[0] * rs * gg.x + bb.x;
    float o1 = v[1] * rs * gg.y + bb.y;
    float o2 = v[2] * rs * gg.z + bb.z;
    float o3 = v[3] * rs * gg.w + bb.w;
    float4 o = {o0, o1, o2, o3};
    ((float4*)(out + (size_t)n * EDIM))[t] = o;
    if (SPLIT) {
        bf16 h0, l0, h1, l1, h2, l2, h3, l3;
        split1(o0, h0, l0); split1(o1, h1, l1);
        split1(o2, h2, l2); split1(o3, h3, l3);
        size_t off = (size_t)n * EDIM + t * 4;
        *(bf162*)(ohi + off)     = bf162(h0, h1);
        *(bf162*)(ohi + off + 2) = bf162(h2, h3);
        *(bf162*)(olo + off)     = bf162(l0, l1);
        *(bf162*)(olo + off + 2) = bf162(l2, l3);
    }
}

// ---------------- launcher ----------------
extern "C" void kernel_launch(void* const* d_in, const int* in_sizes, int n_in,
                              void* d_out, int out_size) {
    const int*   x    = (const int*)  d_in[0];
    const int*   mask = (const int*)  d_in[1];
    const float* emb  = (const float*)d_in[2];
    const float* pos  = (const float*)d_in[3];
    const float* Wq   = (const float*)d_in[4];
    const float* bq   = (const float*)d_in[5];
    const float* Wk   = (const float*)d_in[6];
    const float* bk   = (const float*)d_in[7];
    const float* Wv   = (const float*)d_in[8];
    const float* bv   = (const float*)d_in[9];
    const float* Wo   = (const float*)d_in[10];
    const float* bo   = (const float*)d_in[11];
    const float* g1   = (const float*)d_in[12];
    const float* be1  = (const float*)d_in[13];
    const float* g2   = (const float*)d_in[14];
    const float* be2  = (const float*)d_in[15];
    const float* W1   = (const float*)d_in[16];
    const float* bf1  = (const float*)d_in[17];
    const float* W2   = (const float*)d_in[18];
    const float* bf2  = (const float*)d_in[19];
    float* outp = (float*)d_out;

    float *h32, *p32;
    bf16 *hh, *hl, *qh, *ql, *kh, *kl, *vh, *vl, *ah, *al, *fh, *fl;
    bf16 *wqh, *wql, *wkh, *wkl, *wvh, *wvl, *woh, *wol, *w1h, *w1l, *w2h, *w2l;
    cudaGetSymbolAddress((void**)&h32, g_h32);
    cudaGetSymbolAddress((void**)&p32, g_p32);
    cudaGetSymbolAddress((void**)&hh, g_hh); cudaGetSymbolAddress((void**)&hl, g_hl);
    cudaGetSymbolAddress((void**)&qh, g_qh); cudaGetSymbolAddress((void**)&ql, g_ql);
    cudaGetSymbolAddress((void**)&kh, g_kh); cudaGetSymbolAddress((void**)&kl, g_kl);
    cudaGetSymbolAddress((void**)&vh, g_vh); cudaGetSymbolAddress((void**)&vl, g_vl);
    cudaGetSymbolAddress((void**)&ah, g_ah); cudaGetSymbolAddress((void**)&al, g_al);
    cudaGetSymbolAddress((void**)&fh, g_fh); cudaGetSymbolAddress((void**)&fl, g_fl);
    cudaGetSymbolAddress((void**)&wqh, g_wqh); cudaGetSymbolAddress((void**)&wql, g_wql);
    cudaGetSymbolAddress((void**)&wkh, g_wkh); cudaGetSymbolAddress((void**)&wkl, g_wkl);
    cudaGetSymbolAddress((void**)&wvh, g_wvh); cudaGetSymbolAddress((void**)&wvl, g_wvl);
    cudaGetSymbolAddress((void**)&woh, g_woh); cudaGetSymbolAddress((void**)&wol, g_wol);
    cudaGetSymbolAddress((void**)&w1h, g_w1h); cudaGetSymbolAddress((void**)&w1l, g_w1l);
    cudaGetSymbolAddress((void**)&w2h, g_w2h); cudaGetSymbolAddress((void**)&w2l, g_w2l);

    cudaFuncSetAttribute(attn_tc_kernel, cudaFuncAttributeMaxDynamicSharedMemorySize, ATTN_SMEM);
    cudaFuncSetAttribute(gemm_tc_kernel<0>, cudaFuncAttributeMaxDynamicSharedMemorySize, GEMM_SMEM);
    cudaFuncSetAttribute(gemm_tc_kernel<1>, cudaFuncAttributeMaxDynamicSharedMemorySize, GEMM_SMEM);
    cudaFuncSetAttribute(gemm_tc_kernel<2>, cudaFuncAttributeMaxDynamicSharedMemorySize, GEMM_SMEM);
    cudaFuncSetAttribute(gemm_qkv_kernel, cudaFuncAttributeMaxDynamicSharedMemorySize, GEMM_SMEM);

    split_kernel<<<NLAYER * EDIM * EDIM / 1024, 256>>>(Wq, wqh, wql);
    split_kernel<<<NLAYER * EDIM * EDIM / 1024, 256>>>(Wk, wkh, wkl);
    split_kernel<<<NLAYER * EDIM * EDIM / 1024, 256>>>(Wv, wvh, wvl);
    split_kernel<<<NLAYER * EDIM * EDIM / 1024, 256>>>(Wo, woh, wol);
    split_kernel<<<NLAYER * EDIM * FFDIM / 1024, 256>>>(W1, w1h, w1l);
    split_kernel<<<NLAYER * FFDIM * EDIM / 1024, 256>>>(W2, w2h, w2l);

    embed_kernel<<<(NTOK * EDIM) / 256, 256>>>(x, emb, pos, h32, hh, hl);

    dim3 gE(EDIM / BN, NTOK / BM);
    dim3 gQKV(EDIM / BN, NTOK / BM, 3);
    dim3 gF(FFDIM / BN, NTOK / BM);

    for (int l = 0; l < NLAYER; l++) {
        size_t wo_off = (size_t)l * EDIM * EDIM;
        size_t w1_off = (size_t)l * EDIM * FFDIM;
        size_t w2_off = (size_t)l * FFDIM * EDIM;

        gemm_qkv_kernel<<<gQKV, 128, GEMM_SMEM>>>(
            hh, hl,
            wqh + wo_off, wql + wo_off, wkh + wo_off, wkl + wo_off,
            wvh + wo_off, wvl + wo_off,
            bq + l * EDIM, bk + l * EDIM, bv + l * EDIM,
            qh, ql, kh, kl, vh, vl);

        attn_tc_kernel<<<dim3(SEQ / QT, NB * HEADS), 256, ATTN_SMEM>>>(
            qh, ql, kh, kl, vh, vl, mask, ah, al);

        gemm_tc_kernel<0><<<gE, 128, GEMM_SMEM>>>(
            ah, al, woh + wo_off, wol + wo_off, bo + l * EDIM, p32, nullptr, nullptr,
            EDIM, EDIM);
        ln_kernel<true><<<NTOK, 128>>>(p32, h32, g1 + l * EDIM, be1 + l * EDIM, h32, hh, hl);

        gemm_tc_kernel<2><<<gF, 128, GEMM_SMEM>>>(
            hh, hl, w1h + w1_off, w1l + w1_off, bf1 + l * FFDIM, nullptr, fh, fl,
            EDIM, FFDIM);
        gemm_tc_kernel<0><<<gE, 128, GEMM_SMEM>>>(
            fh, fl, w2h + w2_off, w2l + w2_off, bf2 + l * EDIM, p32, nullptr, nullptr,
            FFDIM, EDIM);

        if (l == NLAYER - 1)
            ln_kernel<false><<<NTOK, 128>>>(p32, h32, g2 + l * EDIM, be2 + l * EDIM,
                                            outp, nullptr, nullptr);
        else
            ln_kernel<true><<<NTOK, 128>>>(p32, h32, g2 + l * EDIM, be2 + l * EDIM,
                                           h32, hh, hl);
    }
}

// round 9
// speedup vs baseline: 1.0562x; 1.0562x over previous
#include <cuda_runtime.h>
#include <cuda_bf16.h>
#include <mma.h>
#include <math.h>
#include <stdint.h>

using namespace nvcuda;

#define NTOK 8192
#define EDIM 512
#define SEQ  2048
#define NB   4
#define HEADS 8
#define HD   64
#define FFDIM 2048
#define NLAYER 2

typedef __nv_bfloat16 bf16;
typedef __nv_bfloat162 bf162;

// ---------------- scratch (device globals; no allocation) ----------------
__device__ float g_h32[NTOK * EDIM];
__device__ float g_p32[NTOK * EDIM];
__device__ bf16 g_hh[NTOK * EDIM], g_hl[NTOK * EDIM];
__device__ bf16 g_qh[NTOK * EDIM], g_ql[NTOK * EDIM];
__device__ bf16 g_kh[NTOK * EDIM], g_kl[NTOK * EDIM];
__device__ bf16 g_vh[NTOK * EDIM], g_vl[NTOK * EDIM];
__device__ bf16 g_ah[NTOK * EDIM], g_al[NTOK * EDIM];
__device__ bf16 g_fh[NTOK * FFDIM], g_fl[NTOK * FFDIM];
__device__ bf16 g_wqh[NLAYER * EDIM * EDIM], g_wql[NLAYER * EDIM * EDIM];
__device__ bf16 g_wkh[NLAYER * EDIM * EDIM], g_wkl[NLAYER * EDIM * EDIM];
__device__ bf16 g_wvh[NLAYER * EDIM * EDIM], g_wvl[NLAYER * EDIM * EDIM];
__device__ bf16 g_woh[NLAYER * EDIM * EDIM], g_wol[NLAYER * EDIM * EDIM];
__device__ bf16 g_w1h[NLAYER * EDIM * FFDIM], g_w1l[NLAYER * EDIM * FFDIM];
__device__ bf16 g_w2h[NLAYER * FFDIM * EDIM], g_w2l[NLAYER * FFDIM * EDIM];

__device__ __forceinline__ void split1(float x, bf16& h, bf16& l) {
    h = __float2bfloat16(x);
    l = __float2bfloat16(x - __bfloat162float(h));
}

__device__ __forceinline__ void cp_async16(void* smem, const void* gmem) {
    unsigned int s = (unsigned int)__cvta_generic_to_shared(smem);
    asm volatile("cp.async.cg.shared.global [%0], [%1], 16;\n" :: "r"(s), "l"(gmem));
}
__device__ __forceinline__ void cp_commit() {
    asm volatile("cp.async.commit_group;\n");
}
template <int N>
__device__ __forceinline__ void cp_wait() {
    asm volatile("cp.async.wait_group %0;\n" :: "n"(N));
}

// ---------------- weight pre-split ----------------
__global__ void split_kernel(const float* __restrict__ src, bf16* __restrict__ hi,
                             bf16* __restrict__ lo) {
    int i = (blockIdx.x * 256 + threadIdx.x) * 4;
    float4 v = *(const float4*)(src + i);
    bf16 h0, l0, h1, l1, h2, l2, h3, l3;
    split1(v.x, h0, l0); split1(v.y, h1, l1);
    split1(v.z, h2, l2); split1(v.w, h3, l3);
    *(bf162*)(hi + i)     = bf162(h0, h1);
    *(bf162*)(hi + i + 2) = bf162(h2, h3);
    *(bf162*)(lo + i)     = bf162(l0, l1);
    *(bf162*)(lo + i + 2) = bf162(l2, l3);
}

// ---------------- embedding + positional (fp32 + split) ----------------
__global__ void embed_kernel(const int* __restrict__ x,
                             const float* __restrict__ emb,
                             const float* __restrict__ pos,
                             float* __restrict__ h,
                             bf16* __restrict__ hh, bf16* __restrict__ hl) {
    int idx = blockIdx.x * blockDim.x + threadIdx.x;
    int n = idx >> 9;
    int e = idx & 511;
    int tok = x[n] + 1;
    int s = n & (SEQ - 1);
    float v = emb[tok * EDIM + e] + pos[s * EDIM + e];
    h[idx] = v;
    bf16 hv, lv;
    split1(v, hv, lv);
    hh[idx] = hv;
    hl[idx] = lv;
}

// ---------------- bf16x3 tensor-core GEMM ----------------
#define BM 128
#define BN 128
#define BK 32
#define SA_STR 56
#define SB_STR 136
#define EPI_STR 68
#define ABUFH (BM * SA_STR)
#define STG_A (2 * ABUFH)
#define BBUFH (BK * SB_STR)
#define STG_B (2 * BBUFH)
#define STG_ELEMS (STG_A + STG_B)
#define NSTAGE 2
#define GEMM_SMEM (NSTAGE * STG_ELEMS * 2)   // 92160 bytes

__device__ __forceinline__
void gemm_load_stage(const bf16* Ah, const bf16* Al, const bf16* Wh, const bf16* Wl,
                     int K, int M, int rowBase, int colBase, int k0,
                     bf16* st, int tid) {
    bf16* sAh = st;
    bf16* sAl = st + ABUFH;
    bf16* sBh = st + STG_A;
    bf16* sBl = st + STG_A + BBUFH;
    #pragma unroll
    for (int i = 0; i < 4; i++) {
        int f = tid + i * 128;
        int r = f >> 2, c = (f & 3) * 8;
        cp_async16(&sAh[r * SA_STR + c], Ah + (size_t)(rowBase + r) * K + k0 + c);
        cp_async16(&sAl[r * SA_STR + c], Al + (size_t)(rowBase + r) * K + k0 + c);
        int rB = f >> 4, cB = (f & 15) * 8;
        cp_async16(&sBh[rB * SB_STR + cB], Wh + (size_t)(k0 + rB) * M + colBase + cB);
        cp_async16(&sBl[rB * SB_STR + cB], Wl + (size_t)(k0 + rB) * M + colBase + cB);
    }
}

// MODE: 0 = fp32 out, 1 = split out, 2 = split + relu out
template <int MODE>
__device__ __forceinline__
void gemm_body(const bf16* Ah, const bf16* Al, const bf16* Wh, const bf16* Wl,
               const float* __restrict__ bias, float* C, bf16* Chi, bf16* Clo,
               int K, int M, int rowBase, int colBase, char* dynsmem) {
    bf16* base = (bf16*)dynsmem;
    int tid = threadIdx.x;
    int lane = tid & 31;
    int wid = tid >> 5;
    int wm = wid & 1;
    int wn = wid >> 1;
    int nk = K / BK;

    wmma::fragment<wmma::accumulator, 16, 16, 16, float> acc[4][4];
    #pragma unroll
    for (int i = 0; i < 4; i++)
        #pragma unroll
        for (int j = 0; j < 4; j++)
            wmma::fill_fragment(acc[i][j], 0.0f);

    gemm_load_stage(Ah, Al, Wh, Wl, K, M, rowBase, colBase, 0, base, tid);
    cp_commit();
    gemm_load_stage(Ah, Al, Wh, Wl, K, M, rowBase, colBase, BK, base + STG_ELEMS, tid);
    cp_commit();

    for (int kc = 0; kc < nk; kc++) {
        cp_wait<1>();
        __syncthreads();

        bf16* st = base + (kc & 1) * STG_ELEMS;
        bf16* sAh = st;
        bf16* sAl = st + ABUFH;
        bf16* sBh = st + STG_A;
        bf16* sBl = st + STG_A + BBUFH;
        #pragma unroll
        for (int ks = 0; ks < BK; ks += 16) {
            wmma::fragment<wmma::matrix_a, 16, 16, 16, bf16, wmma::row_major> ah[4], al[4];
            wmma::fragment<wmma::matrix_b, 16, 16, 16, bf16, wmma::row_major> bh[4], bl[4];
            #pragma unroll
            for (int i = 0; i < 4; i++)
                wmma::load_matrix_sync(ah[i], &sAh[(wm * 64 + i * 16) * SA_STR + ks], SA_STR);
            #pragma unroll
            for (int j = 0; j < 4; j++)
                wmma::load_matrix_sync(bh[j], &sBh[ks * SB_STR + wn * 64 + j * 16], SB_STR);
            #pragma unroll
            for (int i = 0; i < 4; i++)
                #pragma unroll
                for (int j = 0; j < 4; j++)
                    wmma::mma_sync(acc[i][j], ah[i], bh[j], acc[i][j]);
            #pragma unroll
            for (int j = 0; j < 4; j++)
                wmma::load_matrix_sync(bl[j], &sBl[ks * SB_STR + wn * 64 + j * 16], SB_STR);
            #pragma unroll
            for (int i = 0; i < 4; i++)
                #pragma unroll
                for (int j = 0; j < 4; j++)
                    wmma::mma_sync(acc[i][j], ah[i], bl[j], acc[i][j]);
            #pragma unroll
            for (int i = 0; i < 4; i++)
                wmma::load_matrix_sync(al[i], &sAl[(wm * 64 + i * 16) * SA_STR + ks], SA_STR);
            #pragma unroll
            for (int i = 0; i < 4; i++)
                #pragma unroll
                for (int j = 0; j < 4; j++)
                    wmma::mma_sync(acc[i][j], al[i], bh[j], acc[i][j]);
        }
        __syncthreads();

        if (kc + 2 < nk)
            gemm_load_stage(Ah, Al, Wh, Wl, K, M, rowBase, colBase, (kc + 2) * BK,
                            base + (kc & 1) * STG_ELEMS, tid);
        cp_commit();
    }

    cp_wait<0>();
    __syncthreads();

    float* stg = (float*)dynsmem + wid * (64 * EPI_STR);
    #pragma unroll
    for (int i = 0; i < 4; i++)
        #pragma unroll
        for (int j = 0; j < 4; j++)
            wmma::store_matrix_sync(stg + i * 16 * EPI_STR + j * 16, acc[i][j],
                                    EPI_STR, wmma::mem_row_major);
    __syncwarp();

    int rowW = rowBase + wm * 64;
    int colW = colBase + wn * 64;
    #pragma unroll
    for (int it = 0; it < 32; it++) {
        int f = it * 32 + lane;
        int r = f >> 4;
        int c4 = (f & 15) << 2;
        float4 v = *(float4*)(stg + r * EPI_STR + c4);
        float4 bb = *(const float4*)(bias + colW + c4);
        v.x += bb.x; v.y += bb.y; v.z += bb.z; v.w += bb.w;
        if (MODE == 2) {
            v.x = fmaxf(v.x, 0.f); v.y = fmaxf(v.y, 0.f);
            v.z = fmaxf(v.z, 0.f); v.w = fmaxf(v.w, 0.f);
        }
        if (MODE == 0) {
            *(float4*)(C + (size_t)(rowW + r) * M + colW + c4) = v;
        } else {
            bf16 h0, l0, h1, l1, h2, l2, h3, l3;
            split1(v.x, h0, l0); split1(v.y, h1, l1);
            split1(v.z, h2, l2); split1(v.w, h3, l3);
            size_t off = (size_t)(rowW + r) * M + colW + c4;
            *(bf162*)(Chi + off)     = bf162(h0, h1);
            *(bf162*)(Chi + off + 2) = bf162(h2, h3);
            *(bf162*)(Clo + off)     = bf162(l0, l1);
            *(bf162*)(Clo + off + 2) = bf162(l2, l3);
        }
    }
}

template <int MODE>
__global__ __launch_bounds__(128, 2)
void gemm_tc_kernel(const bf16* Ah, const bf16* Al, const bf16* Wh, const bf16* Wl,
                    const float* __restrict__ bias, float* C, bf16* Chi, bf16* Clo,
                    int K, int M) {
    extern __shared__ char dynsmem[];
    gemm_body<MODE>(Ah, Al, Wh, Wl, bias, C, Chi, Clo, K, M,
                    blockIdx.y * BM, blockIdx.x * BN, dynsmem);
}

__global__ __launch_bounds__(128, 2)
void gemm_qkv_kernel(const bf16* Ah, const bf16* Al,
                     const bf16* Wqh, const bf16* Wql, const bf16* Wkh, const bf16* Wkl,
                     const bf16* Wvh, const bf16* Wvl,
                     const float* bq, const float* bk, const float* bv,
                     bf16* qh, bf16* ql, bf16* kh, bf16* kl, bf16* vh, bf16* vl) {
    extern __shared__ char dynsmem[];
    const bf16 *Wh, *Wl;
    const float* bias;
    bf16 *Chi, *Clo;
    if (blockIdx.z == 0)      { Wh = Wqh; Wl = Wql; bias = bq; Chi = qh; Clo = ql; }
    else if (blockIdx.z == 1) { Wh = Wkh; Wl = Wkl; bias = bk; Chi = kh; Clo = kl; }
    else                      { Wh = Wvh; Wl = Wvl; bias = bv; Chi = vh; Clo = vl; }
    gemm_body<1>(Ah, Al, Wh, Wl, bias, nullptr, Chi, Clo, EDIM, EDIM,
                 blockIdx.y * BM, blockIdx.x * BN, dynsmem);
}

// ---------------- tensor-core flash attention: 128-query tile, P/S alias
// 256 threads / 8 warps; warp tile 32x32 on the 128x64 S / O tiles.
// P (hi+lo bf16) aliases the fp32 S/O staging buffer: row stride 272B holds
// either 68 floats (S/O) or 64+64 bf16 (PH|PL).
#define QT 128
#define KSTR 72
#define SSTR 68
#define PSTR 136                              // bf16 stride inside alias region
#define AQH 0
#define AQL (QT * KSTR)                       // 9216
#define AKH (2 * QT * KSTR)                   // 18432
#define AKL (AKH + 64 * KSTR)
#define AVH (AKH + 2 * 64 * KSTR)
#define AVL (AKH + 3 * 64 * KSTR)
#define PH_OFF (AKH + 4 * 64 * KSTR)          // 36864 elems = start of alias region
#define SF_OFF (PH_OFF * 2)                   // byte offset 73728
#define ATTN_SMEM (SF_OFF + QT * SSTR * 4)    // 73728 + 34816 = 108544 bytes

__device__ __forceinline__
void attn_load_kv(const bf16* gh, const bf16* gl, bf16* sb, int offH, int offL,
                  size_t rowG, int colB, int tid) {
    #pragma unroll
    for (int i = 0; i < 2; i++) {
        int f = tid + i * 256;
        int r = f >> 3, c = (f & 7) * 8;
        cp_async16(&sb[offH + r * KSTR + c], gh + (rowG + r) * EDIM + colB + c);
        cp_async16(&sb[offL + r * KSTR + c], gl + (rowG + r) * EDIM + colB + c);
    }
}

__global__ __launch_bounds__(256, 2)
void attn_tc_kernel(const bf16* __restrict__ qh, const bf16* __restrict__ ql,
                    const bf16* __restrict__ kh, const bf16* __restrict__ kl,
                    const bf16* __restrict__ vh, const bf16* __restrict__ vl,
                    const int* __restrict__ mask,
                    bf16* __restrict__ oh, bf16* __restrict__ ol) {
    extern __shared__ char smraw[];
    bf16* sb = (bf16*)smraw;
    float* Sf = (float*)(smraw + SF_OFF);

    int tid = threadIdx.x;
    int wid = tid >> 5;
    int wr = (wid & 3) * 32;          // warp row band
    int wc = (wid >> 2) * 32;         // warp col band
    int b  = blockIdx.y >> 3;
    int hh = blockIdx.y & 7;
    int q0 = blockIdx.x * QT;
    int colB = hh * HD;
    size_t qrow = (size_t)(b * SEQ + q0);
    size_t krow = (size_t)(b * SEQ);

    // stage Q (128 rows, scaled by 1/8)
    {
        bf162 sc = __float2bfloat162_rn(0.125f);
        #pragma unroll
        for (int i = 0; i < 4; i++) {
            int f = tid + i * 256;
            int r = f >> 3, c = (f & 7) * 8;
            uint4 uh = *(const uint4*)(qh + (qrow + r) * EDIM + colB + c);
            uint4 ulo = *(const uint4*)(ql + (qrow + r) * EDIM + colB + c);
            bf162* ph = (bf162*)&uh;
            bf162* pl = (bf162*)&ulo;
            #pragma unroll
            for (int j = 0; j < 4; j++) { ph[j] = __hmul2(ph[j], sc); pl[j] = __hmul2(pl[j], sc); }
            *(uint4*)&sb[AQH + r * KSTR + c] = uh;
            *(uint4*)&sb[AQL + r * KSTR + c] = ulo;
        }
    }

    int rr = tid >> 1;                // 0..127 query row
    int pp = tid & 1;                 // 32-col half
    float o_acc[32];
    #pragma unroll
    for (int i = 0; i < 32; i++) o_acc[i] = 0.f;
    float mrun = -1e30f, lrun = 0.f;

    attn_load_kv(kh, kl, sb, AKH, AKL, krow, colB, tid);
    attn_load_kv(vh, vl, sb, AVH, AVL, krow, colB, tid);
    cp_commit();

    for (int kb = 0; kb < SEQ / 64; kb++) {
        cp_wait<0>();
        __syncthreads();

        // S = Q @ K^T (128x64x64)
        {
            wmma::fragment<wmma::matrix_a, 16, 16, 16, bf16, wmma::row_major> qa_h[2], qa_l[2];
            wmma::fragment<wmma::matrix_b, 16, 16, 16, bf16, wmma::col_major> kb_h[2], kb_l[2];
            wmma::fragment<wmma::accumulator, 16, 16, 16, float> sacc[2][2];
            #pragma unroll
            for (int i = 0; i < 2; i++)
                #pragma unroll
                for (int j = 0; j < 2; j++)
                    wmma::fill_fragment(sacc[i][j], 0.f);
            #pragma unroll
            for (int kk = 0; kk < 4; kk++) {
                #pragma unroll
                for (int i = 0; i < 2; i++) {
                    wmma::load_matrix_sync(qa_h[i], &sb[AQH + (wr + i * 16) * KSTR + kk * 16], KSTR);
                    wmma::load_matrix_sync(qa_l[i], &sb[AQL + (wr + i * 16) * KSTR + kk * 16], KSTR);
                }
                #pragma unroll
                for (int j = 0; j < 2; j++) {
                    wmma::load_matrix_sync(kb_h[j], &sb[AKH + (wc + j * 16) * KSTR + kk * 16], KSTR);
                    wmma::load_matrix_sync(kb_l[j], &sb[AKL + (wc + j * 16) * KSTR + kk * 16], KSTR);
                }
                #pragma unroll
                for (int i = 0; i < 2; i++)
                    #pragma unroll
                    for (int j = 0; j < 2; j++) {
                        wmma::mma_sync(sacc[i][j], qa_h[i], kb_h[j], sacc[i][j]);
                        wmma::mma_sync(sacc[i][j], qa_h[i], kb_l[j], sacc[i][j]);
                        wmma::mma_sync(sacc[i][j], qa_l[i], kb_h[j], sacc[i][j]);
                    }
            }
            #pragma unroll
            for (int i = 0; i < 2; i++)
                #pragma unroll
                for (int j = 0; j < 2; j++)
                    wmma::store_matrix_sync(&Sf[(wr + i * 16) * SSTR + wc + j * 16],
                                            sacc[i][j], SSTR, wmma::mem_row_major);
        }
        __syncthreads();

        if (kb + 1 < SEQ / 64)
            attn_load_kv(kh, kl, sb, AKH, AKL, krow + (kb + 1) * 64, colB, tid);
        cp_commit();

        // softmax: 2 threads/row; read S to regs, syncwarp, write P into alias
        {
            const float* srow = &Sf[rr * SSTR + pp * 32];
            const int4* mrow = (const int4*)(mask + b * SEQ + kb * 64 + pp * 32);
            float s[32];
            #pragma unroll
            for (int i = 0; i < 8; i++) {
                float4 sv = *(const float4*)(srow + i * 4);
                int4 mk = mrow[i];
                s[4 * i + 0] = mk.x ? sv.x : -1e20f;
                s[4 * i + 1] = mk.y ? sv.y : -1e20f;
                s[4 * i + 2] = mk.z ? sv.z : -1e20f;
                s[4 * i + 3] = mk.w ? sv.w : -1e20f;
            }
            __syncwarp();   // all S reads of this row pair complete before P writes
            float mloc = s[0];
            #pragma unroll
            for (int i = 1; i < 32; i++) mloc = fmaxf(mloc, s[i]);
            mloc = fmaxf(mloc, __shfl_xor_sync(0xffffffffu, mloc, 1));
            float mnew = fmaxf(mrun, mloc);
            float corr = __expf(mrun - mnew);
            mrun = mnew;
            float psum = 0.f;
            bf162* ph = (bf162*)&sb[PH_OFF + rr * PSTR + pp * 32];
            bf162* pl = (bf162*)&sb[PH_OFF + rr * PSTR + 64 + pp * 32];
            #pragma unroll
            for (int i = 0; i < 16; i++) {
                float p0 = __expf(s[2 * i] - mnew);
                float p1 = __expf(s[2 * i + 1] - mnew);
                psum += p0 + p1;
                bf16 h0, l0, h1, l1;
                split1(p0, h0, l0); split1(p1, h1, l1);
                ph[i] = bf162(h0, h1);
                pl[i] = bf162(l0, l1);
            }
            psum += __shfl_xor_sync(0xffffffffu, psum, 1);
            lrun = lrun * corr + psum;
            #pragma unroll
            for (int i = 0; i < 32; i++) o_acc[i] *= corr;
        }
        __syncthreads();

        // Opart = P @ V (128x64x64); P read from alias, O stored over it after barrier
        {
            wmma::fragment<wmma::matrix_a, 16, 16, 16, bf16, wmma::row_major> pa_h[2], pa_l[2];
            wmma::fragment<wmma::matrix_b, 16, 16, 16, bf16, wmma::row_major> vb_h[2], vb_l[2];
            wmma::fragment<wmma::accumulator, 16, 16, 16, float> oacc[2][2];
            #pragma unroll
            for (int i = 0; i < 2; i++)
                #pragma unroll
                for (int j = 0; j < 2; j++)
                    wmma::fill_fragment(oacc[i][j], 0.f);
            #pragma unroll
            for (int kk = 0; kk < 4; kk++) {
                #pragma unroll
                for (int i = 0; i < 2; i++) {
                    wmma::load_matrix_sync(pa_h[i], &sb[PH_OFF + (wr + i * 16) * PSTR + kk * 16], PSTR);
                    wmma::load_matrix_sync(pa_l[i], &sb[PH_OFF + (wr + i * 16) * PSTR + 64 + kk * 16], PSTR);
                }
                #pragma unroll
                for (int j = 0; j < 2; j++) {
                    wmma::load_matrix_sync(vb_h[j], &sb[AVH + (kk * 16) * KSTR + wc + j * 16], KSTR);
                    wmma::load_matrix_sync(vb_l[j], &sb[AVL + (kk * 16) * KSTR + wc + j * 16], KSTR);
                }
                #pragma unroll
                for (int i = 0; i < 2; i++)
                    #pragma unroll
                    for (int j = 0; j < 2; j++) {
                        wmma::mma_sync(oacc[i][j], pa_h[i], vb_h[j], oacc[i][j]);
                        wmma::mma_sync(oacc[i][j], pa_h[i], vb_l[j], oacc[i][j]);
                        wmma::mma_sync(oacc[i][j], pa_l[i], vb_h[j], oacc[i][j]);
                    }
            }
            __syncthreads();   // all warps done reading P before O overwrites the alias
            #pragma unroll
            for (int i = 0; i < 2; i++)
                #pragma unroll
                for (int j = 0; j < 2; j++)
                    wmma::store_matrix_sync(&Sf[(wr + i * 16) * SSTR + wc + j * 16],
                                            oacc[i][j], SSTR, wmma::mem_row_major);
        }
        __syncthreads();

        if (kb + 1 < SEQ / 64)
            attn_load_kv(vh, vl, sb, AVH, AVL, krow + (kb + 1) * 64, colB, tid);
        cp_commit();

        // accumulate O part
        {
            const float* orow = &Sf[rr * SSTR + pp * 32];
            #pragma unroll
            for (int i = 0; i < 8; i++) {
                float4 op = *(const float4*)(orow + i * 4);
                o_acc[4 * i + 0] += op.x;
                o_acc[4 * i + 1] += op.y;
                o_acc[4 * i + 2] += op.z;
                o_acc[4 * i + 3] += op.w;
            }
        }
    }

    float inv = 1.f / lrun;
    size_t obase = (qrow + rr) * EDIM + colB + pp * 32;
    #pragma unroll
    for (int i = 0; i < 16; i++) {
        float v0 = o_acc[2 * i] * inv;
        float v1 = o_acc[2 * i + 1] * inv;
        bf16 h0, l0, h1, l1;
        split1(v0, h0, l0); split1(v1, h1, l1);
        *(bf162*)(oh + obase + 2 * i) = bf162(h0, h1);
        *(bf162*)(ol + obase + 2 * i) = bf162(l0, l1);
    }
}

// ---------------- residual + LayerNorm (fp32 out + optional split) ------
template <bool SPLIT>
__global__ __launch_bounds__(128)
void ln_kernel(const float* __restrict__ A, const float* __restrict__ R,
               const float* __restrict__ g, const float* __restrict__ be,
               float* __restrict__ out, bf16* __restrict__ ohi, bf16* __restrict__ olo) {
    __shared__ float red[4];
    int n = blockIdx.x;
    int t = threadIdx.x;
    float4 a = ((const float4*)(A + (size_t)n * EDIM))[t];
    float4 r = ((const float4*)(R + (size_t)n * EDIM))[t];
    float v[4] = {a.x + r.x, a.y + r.y, a.z + r.z, a.w + r.w};

    float s = v[0] + v[1] + v[2] + v[3];
    #pragma unroll
    for (int o = 16; o; o >>= 1) s += __shfl_xor_sync(0xffffffffu, s, o);
    if ((t & 31) == 0) red[t >> 5] = s;
    __syncthreads();
    float mu = (red[0] + red[1] + red[2] + red[3]) * (1.f / EDIM);
    __syncthreads();

    v[0] -= mu; v[1] -= mu; v[2] -= mu; v[3] -= mu;
    float sq = v[0] * v[0] + v[1] * v[1] + v[2] * v[2] + v[3] * v[3];
    #pragma unroll
    for (int o = 16; o; o >>= 1) sq += __shfl_xor_sync(0xffffffffu, sq, o);
    if ((t & 31) == 0) red[t >> 5] = sq;
    __syncthreads();
    float var = (red[0] + red[1] + red[2] + red[3]) * (1.f / EDIM);
    float rs = rsqrtf(var + 1e-6f);

    float4 gg = ((const float4*)g)[t];
    float4 bb = ((const float4*)be)[t];
    float o0 = v[0] * rs * gg.x + bb.x;
    float o1 = v[1] * rs * gg.y + bb.y;
    float o2 = v[2] * rs * gg.z + bb.z;
    float o3 = v[3] * rs * gg.w + bb.w;
    float4 o = {o0, o1, o2, o3};
    ((float4*)(out + (size_t)n * EDIM))[t] = o;
    if (SPLIT) {
        bf16 h0, l0, h1, l1, h2, l2, h3, l3;
        split1(o0, h0, l0); split1(o1, h1, l1);
        split1(o2, h2, l2); split1(o3, h3, l3);
        size_t off = (size_t)n * EDIM + t * 4;
        *(bf162*)(ohi + off)     = bf162(h0, h1);
        *(bf162*)(ohi + off + 2) = bf162(h2, h3);
        *(bf162*)(olo + off)     = bf162(l0, l1);
        *(bf162*)(olo + off + 2) = bf162(l2, l3);
    }
}

// ---------------- launcher ----------------
extern "C" void kernel_launch(void* const* d_in, const int* in_sizes, int n_in,
                              void* d_out, int out_size) {
    const int*   x    = (const int*)  d_in[0];
    const int*   mask = (const int*)  d_in[1];
    const float* emb  = (const float*)d_in[2];
    const float* pos  = (const float*)d_in[3];
    const float* Wq   = (const float*)d_in[4];
    const float* bq   = (const float*)d_in[5];
    const float* Wk   = (const float*)d_in[6];
    const float* bk   = (const float*)d_in[7];
    const float* Wv   = (const float*)d_in[8];
    const float* bv   = (const float*)d_in[9];
    const float* Wo   = (const float*)d_in[10];
    const float* bo   = (const float*)d_in[11];
    const float* g1   = (const float*)d_in[12];
    const float* be1  = (const float*)d_in[13];
    const float* g2   = (const float*)d_in[14];
    const float* be2  = (const float*)d_in[15];
    const float* W1   = (const float*)d_in[16];
    const float* bf1  = (const float*)d_in[17];
    const float* W2   = (const float*)d_in[18];
    const float* bf2  = (const float*)d_in[19];
    float* outp = (float*)d_out;

    float *h32, *p32;
    bf16 *hh, *hl, *qh, *ql, *kh, *kl, *vh, *vl, *ah, *al, *fh, *fl;
    bf16 *wqh, *wql, *wkh, *wkl, *wvh, *wvl, *woh, *wol, *w1h, *w1l, *w2h, *w2l;
    cudaGetSymbolAddress((void**)&h32, g_h32);
    cudaGetSymbolAddress((void**)&p32, g_p32);
    cudaGetSymbolAddress((void**)&hh, g_hh); cudaGetSymbolAddress((void**)&hl, g_hl);
    cudaGetSymbolAddress((void**)&qh, g_qh); cudaGetSymbolAddress((void**)&ql, g_ql);
    cudaGetSymbolAddress((void**)&kh, g_kh); cudaGetSymbolAddress((void**)&kl, g_kl);
    cudaGetSymbolAddress((void**)&vh, g_vh); cudaGetSymbolAddress((void**)&vl, g_vl);
    cudaGetSymbolAddress((void**)&ah, g_ah); cudaGetSymbolAddress((void**)&al, g_al);
    cudaGetSymbolAddress((void**)&fh, g_fh); cudaGetSymbolAddress((void**)&fl, g_fl);
    cudaGetSymbolAddress((void**)&wqh, g_wqh); cudaGetSymbolAddress((void**)&wql, g_wql);
    cudaGetSymbolAddress((void**)&wkh, g_wkh); cudaGetSymbolAddress((void**)&wkl, g_wkl);
    cudaGetSymbolAddress((void**)&wvh, g_wvh); cudaGetSymbolAddress((void**)&wvl, g_wvl);
    cudaGetSymbolAddress((void**)&woh, g_woh); cudaGetSymbolAddress((void**)&wol, g_wol);
    cudaGetSymbolAddress((void**)&w1h, g_w1h); cudaGetSymbolAddress((void**)&w1l, g_w1l);
    cudaGetSymbolAddress((void**)&w2h, g_w2h); cudaGetSymbolAddress((void**)&w2l, g_w2l);

    cudaFuncSetAttribute(attn_tc_kernel, cudaFuncAttributeMaxDynamicSharedMemorySize, ATTN_SMEM);
    cudaFuncSetAttribute(gemm_tc_kernel<0>, cudaFuncAttributeMaxDynamicSharedMemorySize, GEMM_SMEM);
    cudaFuncSetAttribute(gemm_tc_kernel<1>, cudaFuncAttributeMaxDynamicSharedMemorySize, GEMM_SMEM);
    cudaFuncSetAttribute(gemm_tc_kernel<2>, cudaFuncAttributeMaxDynamicSharedMemorySize, GEMM_SMEM);
    cudaFuncSetAttribute(gemm_qkv_kernel, cudaFuncAttributeMaxDynamicSharedMemorySize, GEMM_SMEM);

    split_kernel<<<NLAYER * EDIM * EDIM / 1024, 256>>>(Wq, wqh, wql);
    split_kernel<<<NLAYER * EDIM * EDIM / 1024, 256>>>(Wk, wkh, wkl);
    split_kernel<<<NLAYER * EDIM * EDIM / 1024, 256>>>(Wv, wvh, wvl);
    split_kernel<<<NLAYER * EDIM * EDIM / 1024, 256>>>(Wo, woh, wol);
    split_kernel<<<NLAYER * EDIM * FFDIM / 1024, 256>>>(W1, w1h, w1l);
    split_kernel<<<NLAYER * FFDIM * EDIM / 1024, 256>>>(W2, w2h, w2l);

    embed_kernel<<<(NTOK * EDIM) / 256, 256>>>(x, emb, pos, h32, hh, hl);

    dim3 gE(EDIM / BN, NTOK / BM);
    dim3 gQKV(EDIM / BN, NTOK / BM, 3);
    dim3 gF(FFDIM / BN, NTOK / BM);

    for (int l = 0; l < NLAYER; l++) {
        size_t wo_off = (size_t)l * EDIM * EDIM;
        size_t w1_off = (size_t)l * EDIM * FFDIM;
        size_t w2_off = (size_t)l * FFDIM * EDIM;

        gemm_qkv_kernel<<<gQKV, 128, GEMM_SMEM>>>(
            hh, hl,
            wqh + wo_off, wql + wo_off, wkh + wo_off, wkl + wo_off,
            wvh + wo_off, wvl + wo_off,
            bq + l * EDIM, bk + l * EDIM, bv + l * EDIM,
            qh, ql, kh, kl, vh, vl);

        attn_tc_kernel<<<dim3(SEQ / QT, NB * HEADS), 256, ATTN_SMEM>>>(
            qh, ql, kh, kl, vh, vl, mask, ah, al);

        gemm_tc_kernel<0><<<gE, 128, GEMM_SMEM>>>(
            ah, al, woh + wo_off, wol + wo_off, bo + l * EDIM, p32, nullptr, nullptr,
            EDIM, EDIM);
        ln_kernel<true><<<NTOK, 128>>>(p32, h32, g1 + l * EDIM, be1 + l * EDIM, h32, hh, hl);

        gemm_tc_kernel<2><<<gF, 128, GEMM_SMEM>>>(
            hh, hl, w1h + w1_off, w1l + w1_off, bf1 + l * FFDIM, nullptr, fh, fl,
            EDIM, FFDIM);
        gemm_tc_kernel<0><<<gE, 128, GEMM_SMEM>>>(
            fh, fl, w2h + w2_off, w2l + w2_off, bf2 + l * EDIM, p32, nullptr, nullptr,
            FFDIM, EDIM);

        if (l == NLAYER - 1)
            ln_kernel<false><<<NTOK, 128>>>(p32, h32, g2 + l * EDIM, be2 + l * EDIM,
                                            outp, nullptr, nullptr);
        else
            ln_kernel<true><<<NTOK, 128>>>(p32, h32, g2 + l * EDIM, be2 + l * EDIM,
                                           h32, hh, hl);
    }
}

// round 12
// speedup vs baseline: 1.1062x; 1.0473x over previous
#include <cuda_runtime.h>
#include <cuda_bf16.h>
#include <mma.h>
#include <math.h>
#include <stdint.h>

using namespace nvcuda;

#define NTOK 8192
#define EDIM 512
#define SEQ  2048
#define NB   4
#define HEADS 8
#define HD   64
#define FFDIM 2048
#define NLAYER 2

typedef __nv_bfloat16 bf16;
typedef __nv_bfloat162 bf162;

// ---------------- scratch (device globals; no allocation) ----------------
__device__ float g_h32[NTOK * EDIM];
__device__ float g_p32[NTOK * EDIM];
__device__ bf16 g_hh[NTOK * EDIM], g_hl[NTOK * EDIM];
__device__ bf16 g_qh[NTOK * EDIM], g_ql[NTOK * EDIM];
__device__ bf16 g_kh[NTOK * EDIM], g_kl[NTOK * EDIM];
__device__ bf16 g_vh[NTOK * EDIM], g_vl[NTOK * EDIM];
__device__ bf16 g_ah[NTOK * EDIM], g_al[NTOK * EDIM];
__device__ bf16 g_fh[NTOK * FFDIM], g_fl[NTOK * FFDIM];
__device__ bf16 g_wqh[NLAYER * EDIM * EDIM], g_wql[NLAYER * EDIM * EDIM];
__device__ bf16 g_wkh[NLAYER * EDIM * EDIM], g_wkl[NLAYER * EDIM * EDIM];
__device__ bf16 g_wvh[NLAYER * EDIM * EDIM], g_wvl[NLAYER * EDIM * EDIM];
__device__ bf16 g_woh[NLAYER * EDIM * EDIM], g_wol[NLAYER * EDIM * EDIM];
__device__ bf16 g_w1h[NLAYER * EDIM * FFDIM], g_w1l[NLAYER * EDIM * FFDIM];
__device__ bf16 g_w2h[NLAYER * FFDIM * EDIM], g_w2l[NLAYER * FFDIM * EDIM];

__device__ __forceinline__ void split1(float x, bf16& h, bf16& l) {
    h = __float2bfloat16(x);
    l = __float2bfloat16(x - __bfloat162float(h));
}

__device__ __forceinline__ void cp_async16(void* smem, const void* gmem) {
    unsigned int s = (unsigned int)__cvta_generic_to_shared(smem);
    asm volatile("cp.async.cg.shared.global [%0], [%1], 16;\n" :: "r"(s), "l"(gmem));
}
__device__ __forceinline__ void cp_commit() {
    asm volatile("cp.async.commit_group;\n");
}
template <int N>
__device__ __forceinline__ void cp_wait() {
    asm volatile("cp.async.wait_group %0;\n" :: "n"(N));
}

// ---------------- weight pre-split ----------------
__global__ void split_kernel(const float* __restrict__ src, bf16* __restrict__ hi,
                             bf16* __restrict__ lo) {
    int i = (blockIdx.x * 256 + threadIdx.x) * 4;
    float4 v = *(const float4*)(src + i);
    bf16 h0, l0, h1, l1, h2, l2, h3, l3;
    split1(v.x, h0, l0); split1(v.y, h1, l1);
    split1(v.z, h2, l2); split1(v.w, h3, l3);
    *(bf162*)(hi + i)     = bf162(h0, h1);
    *(bf162*)(hi + i + 2) = bf162(h2, h3);
    *(bf162*)(lo + i)     = bf162(l0, l1);
    *(bf162*)(lo + i + 2) = bf162(l2, l3);
}

// ---------------- embedding + positional (fp32 + split) ----------------
__global__ void embed_kernel(const int* __restrict__ x,
                             const float* __restrict__ emb,
                             const float* __restrict__ pos,
                             float* __restrict__ h,
                             bf16* __restrict__ hh, bf16* __restrict__ hl) {
    int idx = blockIdx.x * blockDim.x + threadIdx.x;
    int n = idx >> 9;
    int e = idx & 511;
    int tok = x[n] + 1;
    int s = n & (SEQ - 1);
    float v = emb[tok * EDIM + e] + pos[s * EDIM + e];
    h[idx] = v;
    bf16 hv, lv;
    split1(v, hv, lv);
    hh[idx] = hv;
    hl[idx] = lv;
}

// ---------------- bf16x3 tensor-core GEMM ----------------
#define BM 128
#define BN 128
#define BK 32
#define SA_STR 56
#define SB_STR 136
#define EPI_STR 68
#define ABUFH (BM * SA_STR)
#define STG_A (2 * ABUFH)
#define BBUFH (BK * SB_STR)
#define STG_B (2 * BBUFH)
#define STG_ELEMS (STG_A + STG_B)
#define NSTAGE 2
#define GEMM_SMEM (NSTAGE * STG_ELEMS * 2)   // 92160 bytes

__device__ __forceinline__
void gemm_load_stage(const bf16* Ah, const bf16* Al, const bf16* Wh, const bf16* Wl,
                     int K, int M, int rowBase, int colBase, int k0,
                     bf16* st, int tid) {
    bf16* sAh = st;
    bf16* sAl = st + ABUFH;
    bf16* sBh = st + STG_A;
    bf16* sBl = st + STG_A + BBUFH;
    #pragma unroll
    for (int i = 0; i < 4; i++) {
        int f = tid + i * 128;
        int r = f >> 2, c = (f & 3) * 8;
        cp_async16(&sAh[r * SA_STR + c], Ah + (size_t)(rowBase + r) * K + k0 + c);
        cp_async16(&sAl[r * SA_STR + c], Al + (size_t)(rowBase + r) * K + k0 + c);
        int rB = f >> 4, cB = (f & 15) * 8;
        cp_async16(&sBh[rB * SB_STR + cB], Wh + (size_t)(k0 + rB) * M + colBase + cB);
        cp_async16(&sBl[rB * SB_STR + cB], Wl + (size_t)(k0 + rB) * M + colBase + cB);
    }
}

// MODE: 0 = fp32 out, 1 = split out, 2 = split + relu out
template <int MODE>
__device__ __forceinline__
void gemm_body(const bf16* Ah, const bf16* Al, const bf16* Wh, const bf16* Wl,
               const float* __restrict__ bias, float* C, bf16* Chi, bf16* Clo,
               int K, int M, int rowBase, int colBase, char* dynsmem) {
    bf16* base = (bf16*)dynsmem;
    int tid = threadIdx.x;
    int lane = tid & 31;
    int wid = tid >> 5;
    int wm = wid & 1;
    int wn = wid >> 1;
    int nk = K / BK;

    wmma::fragment<wmma::accumulator, 16, 16, 16, float> acc[4][4];
    #pragma unroll
    for (int i = 0; i < 4; i++)
        #pragma unroll
        for (int j = 0; j < 4; j++)
            wmma::fill_fragment(acc[i][j], 0.0f);

    gemm_load_stage(Ah, Al, Wh, Wl, K, M, rowBase, colBase, 0, base, tid);
    cp_commit();
    gemm_load_stage(Ah, Al, Wh, Wl, K, M, rowBase, colBase, BK, base + STG_ELEMS, tid);
    cp_commit();

    for (int kc = 0; kc < nk; kc++) {
        cp_wait<1>();
        __syncthreads();

        bf16* st = base + (kc & 1) * STG_ELEMS;
        bf16* sAh = st;
        bf16* sAl = st + ABUFH;
        bf16* sBh = st + STG_A;
        bf16* sBl = st + STG_A + BBUFH;
        #pragma unroll
        for (int ks = 0; ks < BK; ks += 16) {
            wmma::fragment<wmma::matrix_a, 16, 16, 16, bf16, wmma::row_major> ah[4], al[4];
            wmma::fragment<wmma::matrix_b, 16, 16, 16, bf16, wmma::row_major> bh[4], bl[4];
            #pragma unroll
            for (int i = 0; i < 4; i++)
                wmma::load_matrix_sync(ah[i], &sAh[(wm * 64 + i * 16) * SA_STR + ks], SA_STR);
            #pragma unroll
            for (int j = 0; j < 4; j++)
                wmma::load_matrix_sync(bh[j], &sBh[ks * SB_STR + wn * 64 + j * 16], SB_STR);
            #pragma unroll
            for (int i = 0; i < 4; i++)
                #pragma unroll
                for (int j = 0; j < 4; j++)
                    wmma::mma_sync(acc[i][j], ah[i], bh[j], acc[i][j]);
            #pragma unroll
            for (int j = 0; j < 4; j++)
                wmma::load_matrix_sync(bl[j], &sBl[ks * SB_STR + wn * 64 + j * 16], SB_STR);
            #pragma unroll
            for (int i = 0; i < 4; i++)
                #pragma unroll
                for (int j = 0; j < 4; j++)
                    wmma::mma_sync(acc[i][j], ah[i], bl[j], acc[i][j]);
            #pragma unroll
            for (int i = 0; i < 4; i++)
                wmma::load_matrix_sync(al[i], &sAl[(wm * 64 + i * 16) * SA_STR + ks], SA_STR);
            #pragma unroll
            for (int i = 0; i < 4; i++)
                #pragma unroll
                for (int j = 0; j < 4; j++)
                    wmma::mma_sync(acc[i][j], al[i], bh[j], acc[i][j]);
        }
        __syncthreads();

        if (kc + 2 < nk)
            gemm_load_stage(Ah, Al, Wh, Wl, K, M, rowBase, colBase, (kc + 2) * BK,
                            base + (kc & 1) * STG_ELEMS, tid);
        cp_commit();
    }

    cp_wait<0>();
    __syncthreads();

    float* stg = (float*)dynsmem + wid * (64 * EPI_STR);
    #pragma unroll
    for (int i = 0; i < 4; i++)
        #pragma unroll
        for (int j = 0; j < 4; j++)
            wmma::store_matrix_sync(stg + i * 16 * EPI_STR + j * 16, acc[i][j],
                                    EPI_STR, wmma::mem_row_major);
    __syncwarp();

    int rowW = rowBase + wm * 64;
    int colW = colBase + wn * 64;
    #pragma unroll
    for (int it = 0; it < 32; it++) {
        int f = it * 32 + lane;
        int r = f >> 4;
        int c4 = (f & 15) << 2;
        float4 v = *(float4*)(stg + r * EPI_STR + c4);
        float4 bb = *(const float4*)(bias + colW + c4);
        v.x += bb.x; v.y += bb.y; v.z += bb.z; v.w += bb.w;
        if (MODE == 2) {
            v.x = fmaxf(v.x, 0.f); v.y = fmaxf(v.y, 0.f);
            v.z = fmaxf(v.z, 0.f); v.w = fmaxf(v.w, 0.f);
        }
        if (MODE == 0) {
            *(float4*)(C + (size_t)(rowW + r) * M + colW + c4) = v;
        } else {
            bf16 h0, l0, h1, l1, h2, l2, h3, l3;
            split1(v.x, h0, l0); split1(v.y, h1, l1);
            split1(v.z, h2, l2); split1(v.w, h3, l3);
            size_t off = (size_t)(rowW + r) * M + colW + c4;
            *(bf162*)(Chi + off)     = bf162(h0, h1);
            *(bf162*)(Chi + off + 2) = bf162(h2, h3);
            *(bf162*)(Clo + off)     = bf162(l0, l1);
            *(bf162*)(Clo + off + 2) = bf162(l2, l3);
        }
    }
}

template <int MODE>
__global__ __launch_bounds__(128, 2)
void gemm_tc_kernel(const bf16* Ah, const bf16* Al, const bf16* Wh, const bf16* Wl,
                    const float* __restrict__ bias, float* C, bf16* Chi, bf16* Clo,
                    int K, int M) {
    extern __shared__ char dynsmem[];
    gemm_body<MODE>(Ah, Al, Wh, Wl, bias, C, Chi, Clo, K, M,
                    blockIdx.y * BM, blockIdx.x * BN, dynsmem);
}

__global__ __launch_bounds__(128, 2)
void gemm_qkv_kernel(const bf16* Ah, const bf16* Al,
                     const bf16* Wqh, const bf16* Wql, const bf16* Wkh, const bf16* Wkl,
                     const bf16* Wvh, const bf16* Wvl,
                     const float* bq, const float* bk, const float* bv,
                     bf16* qh, bf16* ql, bf16* kh, bf16* kl, bf16* vh, bf16* vl) {
    extern __shared__ char dynsmem[];
    const bf16 *Wh, *Wl;
    const float* bias;
    bf16 *Chi, *Clo;
    if (blockIdx.z == 0)      { Wh = Wqh; Wl = Wql; bias = bq; Chi = qh; Clo = ql; }
    else if (blockIdx.z == 1) { Wh = Wkh; Wl = Wkl; bias = bk; Chi = kh; Clo = kl; }
    else                      { Wh = Wvh; Wl = Wvl; bias = bv; Chi = vh; Clo = vl; }
    gemm_body<1>(Ah, Al, Wh, Wl, bias, nullptr, Chi, Clo, EDIM, EDIM,
                 blockIdx.y * BM, blockIdx.x * BN, dynsmem);
}

// ---------------- tensor-core flash attention: 128-query tile, P/S alias
// P stored as plain bf16 (hi only): P*V = Ph*Vh + Ph*Vl (2-term).
#define QT 128
#define KSTR 72
#define SSTR 68
#define PSTR 136
#define AQH 0
#define AQL (QT * KSTR)
#define AKH (2 * QT * KSTR)
#define AKL (AKH + 64 * KSTR)
#define AVH (AKH + 2 * 64 * KSTR)
#define AVL (AKH + 3 * 64 * KSTR)
#define PH_OFF (AKH + 4 * 64 * KSTR)
#define SF_OFF (PH_OFF * 2)
#define ATTN_SMEM (SF_OFF + QT * SSTR * 4)    // 108544 bytes

__device__ __forceinline__
void attn_load_kv(const bf16* gh, const bf16* gl, bf16* sb, int offH, int offL,
                  size_t rowG, int colB, int tid) {
    #pragma unroll
    for (int i = 0; i < 2; i++) {
        int f = tid + i * 256;
        int r = f >> 3, c = (f & 7) * 8;
        cp_async16(&sb[offH + r * KSTR + c], gh + (rowG + r) * EDIM + colB + c);
        cp_async16(&sb[offL + r * KSTR + c], gl + (rowG + r) * EDIM + colB + c);
    }
}

__global__ __launch_bounds__(256, 2)
void attn_tc_kernel(const bf16* __restrict__ qh, const bf16* __restrict__ ql,
                    const bf16* __restrict__ kh, const bf16* __restrict__ kl,
                    const bf16* __restrict__ vh, const bf16* __restrict__ vl,
                    const int* __restrict__ mask,
                    bf16* __restrict__ oh, bf16* __restrict__ ol) {
    extern __shared__ char smraw[];
    bf16* sb = (bf16*)smraw;
    float* Sf = (float*)(smraw + SF_OFF);

    int tid = threadIdx.x;
    int wid = tid >> 5;
    int wr = (wid & 3) * 32;
    int wc = (wid >> 2) * 32;
    int b  = blockIdx.y >> 3;
    int hh = blockIdx.y & 7;
    int q0 = blockIdx.x * QT;
    int colB = hh * HD;
    size_t qrow = (size_t)(b * SEQ + q0);
    size_t krow = (size_t)(b * SEQ);

    {
        bf162 sc = __float2bfloat162_rn(0.125f);
        #pragma unroll
        for (int i = 0; i < 4; i++) {
            int f = tid + i * 256;
            int r = f >> 3, c = (f & 7) * 8;
            uint4 uh = *(const uint4*)(qh + (qrow + r) * EDIM + colB + c);
            uint4 ulo = *(const uint4*)(ql + (qrow + r) * EDIM + colB + c);
            bf162* ph = (bf162*)&uh;
            bf162* pl = (bf162*)&ulo;
            #pragma unroll
            for (int j = 0; j < 4; j++) { ph[j] = __hmul2(ph[j], sc); pl[j] = __hmul2(pl[j], sc); }
            *(uint4*)&sb[AQH + r * KSTR + c] = uh;
            *(uint4*)&sb[AQL + r * KSTR + c] = ulo;
        }
    }

    int rr = tid >> 1;
    int pp = tid & 1;
    float o_acc[32];
    #pragma unroll
    for (int i = 0; i < 32; i++) o_acc[i] = 0.f;
    float mrun = -1e30f, lrun = 0.f;

    attn_load_kv(kh, kl, sb, AKH, AKL, krow, colB, tid);
    attn_load_kv(vh, vl, sb, AVH, AVL, krow, colB, tid);
    cp_commit();

    for (int kb = 0; kb < SEQ / 64; kb++) {
        cp_wait<0>();
        __syncthreads();

        // S = Q @ K^T (128x64x64), bf16x3
        {
            wmma::fragment<wmma::matrix_a, 16, 16, 16, bf16, wmma::row_major> qa_h[2], qa_l[2];
            wmma::fragment<wmma::matrix_b, 16, 16, 16, bf16, wmma::col_major> kb_h[2], kb_l[2];
            wmma::fragment<wmma::accumulator, 16, 16, 16, float> sacc[2][2];
            #pragma unroll
            for (int i = 0; i < 2; i++)
                #pragma unroll
                for (int j = 0; j < 2; j++)
                    wmma::fill_fragment(sacc[i][j], 0.f);
            #pragma unroll
            for (int kk = 0; kk < 4; kk++) {
                #pragma unroll
                for (int i = 0; i < 2; i++) {
                    wmma::load_matrix_sync(qa_h[i], &sb[AQH + (wr + i * 16) * KSTR + kk * 16], KSTR);
                    wmma::load_matrix_sync(qa_l[i], &sb[AQL + (wr + i * 16) * KSTR + kk * 16], KSTR);
                }
                #pragma unroll
                for (int j = 0; j < 2; j++) {
                    wmma::load_matrix_sync(kb_h[j], &sb[AKH + (wc + j * 16) * KSTR + kk * 16], KSTR);
                    wmma::load_matrix_sync(kb_l[j], &sb[AKL + (wc + j * 16) * KSTR + kk * 16], KSTR);
                }
                #pragma unroll
                for (int i = 0; i < 2; i++)
                    #pragma unroll
                    for (int j = 0; j < 2; j++) {
                        wmma::mma_sync(sacc[i][j], qa_h[i], kb_h[j], sacc[i][j]);
                        wmma::mma_sync(sacc[i][j], qa_h[i], kb_l[j], sacc[i][j]);
                        wmma::mma_sync(sacc[i][j], qa_l[i], kb_h[j], sacc[i][j]);
                    }
            }
            #pragma unroll
            for (int i = 0; i < 2; i++)
                #pragma unroll
                for (int j = 0; j < 2; j++)
                    wmma::store_matrix_sync(&Sf[(wr + i * 16) * SSTR + wc + j * 16],
                                            sacc[i][j], SSTR, wmma::mem_row_major);
        }
        __syncthreads();

        if (kb + 1 < SEQ / 64)
            attn_load_kv(kh, kl, sb, AKH, AKL, krow + (kb + 1) * 64, colB, tid);
        cp_commit();

        // softmax: 2 threads/row; P stored hi-only
        {
            const float* srow = &Sf[rr * SSTR + pp * 32];
            const int4* mrow = (const int4*)(mask + b * SEQ + kb * 64 + pp * 32);
            float s[32];
            #pragma unroll
            for (int i = 0; i < 8; i++) {
                float4 sv = *(const float4*)(srow + i * 4);
                int4 mk = mrow[i];
                s[4 * i + 0] = mk.x ? sv.x : -1e20f;
                s[4 * i + 1] = mk.y ? sv.y : -1e20f;
                s[4 * i + 2] = mk.z ? sv.z : -1e20f;
                s[4 * i + 3] = mk.w ? sv.w : -1e20f;
            }
            __syncwarp();
            float mloc = s[0];
            #pragma unroll
            for (int i = 1; i < 32; i++) mloc = fmaxf(mloc, s[i]);
            mloc = fmaxf(mloc, __shfl_xor_sync(0xffffffffu, mloc, 1));
            float mnew = fmaxf(mrun, mloc);
            float corr = __expf(mrun - mnew);
            mrun = mnew;
            float psum = 0.f;
            bf162* ph = (bf162*)&sb[PH_OFF + rr * PSTR + pp * 32];
            #pragma unroll
            for (int i = 0; i < 16; i++) {
                float p0 = __expf(s[2 * i] - mnew);
                float p1 = __expf(s[2 * i + 1] - mnew);
                psum += p0 + p1;
                ph[i] = bf162(__float2bfloat16(p0), __float2bfloat16(p1));
            }
            psum += __shfl_xor_sync(0xffffffffu, psum, 1);
            lrun = lrun * corr + psum;
            #pragma unroll
            for (int i = 0; i < 32; i++) o_acc[i] *= corr;
        }
        __syncthreads();

        // Opart = Ph @ (Vh + Vl)  (2-term)
        {
            wmma::fragment<wmma::matrix_a, 16, 16, 16, bf16, wmma::row_major> pa_h[2];
            wmma::fragment<wmma::matrix_b, 16, 16, 16, bf16, wmma::row_major> vb_h[2], vb_l[2];
            wmma::fragment<wmma::accumulator, 16, 16, 16, float> oacc[2][2];
            #pragma unroll
            for (int i = 0; i < 2; i++)
                #pragma unroll
                for (int j = 0; j < 2; j++)
                    wmma::fill_fragment(oacc[i][j], 0.f);
            #pragma unroll
            for (int kk = 0; kk < 4; kk++) {
                #pragma unroll
                for (int i = 0; i < 2; i++)
                    wmma::load_matrix_sync(pa_h[i], &sb[PH_OFF + (wr + i * 16) * PSTR + kk * 16], PSTR);
                #pragma unroll
                for (int j = 0; j < 2; j++) {
                    wmma::load_matrix_sync(vb_h[j], &sb[AVH + (kk * 16) * KSTR + wc + j * 16], KSTR);
                    wmma::load_matrix_sync(vb_l[j], &sb[AVL + (kk * 16) * KSTR + wc + j * 16], KSTR);
                }
                #pragma unroll
                for (int i = 0; i < 2; i++)
                    #pragma unroll
                    for (int j = 0; j < 2; j++) {
                        wmma::mma_sync(oacc[i][j], pa_h[i], vb_h[j], oacc[i][j]);
                        wmma::mma_sync(oacc[i][j], pa_h[i], vb_l[j], oacc[i][j]);
                    }
            }
            __syncthreads();
            #pragma unroll
            for (int i = 0; i < 2; i++)
                #pragma unroll
                for (int j = 0; j < 2; j++)
                    wmma::store_matrix_sync(&Sf[(wr + i * 16) * SSTR + wc + j * 16],
                                            oacc[i][j], SSTR, wmma::mem_row_major);
        }
        __syncthreads();

        if (kb + 1 < SEQ / 64)
            attn_load_kv(vh, vl, sb, AVH, AVL, krow + (kb + 1) * 64, colB, tid);
        cp_commit();

        {
            const float* orow = &Sf[rr * SSTR + pp * 32];
            #pragma unroll
            for (int i = 0; i < 8; i++) {
                float4 op = *(const float4*)(orow + i * 4);
                o_acc[4 * i + 0] += op.x;
                o_acc[4 * i + 1] += op.y;
                o_acc[4 * i + 2] += op.z;
                o_acc[4 * i + 3] += op.w;
            }
        }
    }

    float inv = 1.f / lrun;
    size_t obase = (qrow + rr) * EDIM + colB + pp * 32;
    #pragma unroll
    for (int i = 0; i < 16; i++) {
        float v0 = o_acc[2 * i] * inv;
        float v1 = o_acc[2 * i + 1] * inv;
        bf16 h0, l0, h1, l1;
        split1(v0, h0, l0); split1(v1, h1, l1);
        *(bf162*)(oh + obase + 2 * i) = bf162(h0, h1);
        *(bf162*)(ol + obase + 2 * i) = bf162(l0, l1);
    }
}

// ---------------- residual + LayerNorm (fp32 out + optional split) ------
template <bool SPLIT>
__global__ __launch_bounds__(128)
void ln_kernel(const float* __restrict__ A, const float* __restrict__ R,
               const float* __restrict__ g, const float* __restrict__ be,
               float* __restrict__ out, bf16* __restrict__ ohi, bf16* __restrict__ olo) {
    __shared__ float red[4];
    int n = blockIdx.x;
    int t = threadIdx.x;
    float4 a = ((const float4*)(A + (size_t)n * EDIM))[t];
    float4 r = ((const float4*)(R + (size_t)n * EDIM))[t];
    float v[4] = {a.x + r.x, a.y + r.y, a.z + r.z, a.w + r.w};

    float s = v[0] + v[1] + v[2] + v[3];
    #pragma unroll
    for (int o = 16; o; o >>= 1) s += __shfl_xor_sync(0xffffffffu, s, o);
    if ((t & 31) == 0) red[t >> 5] = s;
    __syncthreads();
    float mu = (red[0] + red[1] + red[2] + red[3]) * (1.f / EDIM);
    __syncthreads();

    v[0] -= mu; v[1] -= mu; v[2] -= mu; v[3] -= mu;
    float sq = v[0] * v[0] + v[1] * v[1] + v[2] * v[2] + v[3] * v[3];
    #pragma unroll
    for (int o = 16; o; o >>= 1) sq += __shfl_xor_sync(0xffffffffu, sq, o);
    if ((t & 31) == 0) red[t >> 5] = sq;
    __syncthreads();
    float var = (red[0] + red[1] + red[2] + red[3]) * (1.f / EDIM);
    float rs = rsqrtf(var + 1e-6f);

    float4 gg = ((const float4*)g)[t];
    float4 bb = ((const float4*)be)[t];
    float o0 = v[0] * rs * gg.x + bb.x;
    float o1 = v[1] * rs * gg.y + bb.y;
    float o2 = v[2] * rs * gg.z + bb.z;
    float o3 = v[3] * rs * gg.w + bb.w;
    float4 o = {o0, o1, o2, o3};
    ((float4*)(out + (size_t)n * EDIM))[t] = o;
    if (SPLIT) {
        bf16 h0, l0, h1, l1, h2, l2, h3, l3;
        split1(o0, h0, l0); split1(o1, h1, l1);
        split1(o2, h2, l2); split1(o3, h3, l3);
        size_t off = (size_t)n * EDIM + t * 4;
        *(bf162*)(ohi + off)     = bf162(h0, h1);
        *(bf162*)(ohi + off + 2) = bf162(h2, h3);
        *(bf162*)(olo + off)     = bf162(l0, l1);
        *(bf162*)(olo + off + 2) = bf162(l2, l3);
    }
}

// ---------------- launcher ----------------
extern "C" void kernel_launch(void* const* d_in, const int* in_sizes, int n_in,
                              void* d_out, int out_size) {
    const int*   x    = (const int*)  d_in[0];
    const int*   mask = (const int*)  d_in[1];
    const float* emb  = (const float*)d_in[2];
    const float* pos  = (const float*)d_in[3];
    const float* Wq   = (const float*)d_in[4];
    const float* bq   = (const float*)d_in[5];
    const float* Wk   = (const float*)d_in[6];
    const float* bk   = (const float*)d_in[7];
    const float* Wv   = (const float*)d_in[8];
    const float* bv   = (const float*)d_in[9];
    const float* Wo   = (const float*)d_in[10];
    const float* bo   = (const float*)d_in[11];
    const float* g1   = (const float*)d_in[12];
    const float* be1  = (const float*)d_in[13];
    const float* g2   = (const float*)d_in[14];
    const float* be2  = (const float*)d_in[15];
    const float* W1   = (const float*)d_in[16];
    const float* bf1  = (const float*)d_in[17];
    const float* W2   = (const float*)d_in[18];
    const float* bf2  = (const float*)d_in[19];
    float* outp = (float*)d_out;

    float *h32, *p32;
    bf16 *hh, *hl, *qh, *ql, *kh, *kl, *vh, *vl, *ah, *al, *fh, *fl;
    bf16 *wqh, *wql, *wkh, *wkl, *wvh, *wvl, *woh, *wol, *w1h, *w1l, *w2h, *w2l;
    cudaGetSymbolAddress((void**)&h32, g_h32);
    cudaGetSymbolAddress((void**)&p32, g_p32);
    cudaGetSymbolAddress((void**)&hh, g_hh); cudaGetSymbolAddress((void**)&hl, g_hl);
    cudaGetSymbolAddress((void**)&qh, g_qh); cudaGetSymbolAddress((void**)&ql, g_ql);
    cudaGetSymbolAddress((void**)&kh, g_kh); cudaGetSymbolAddress((void**)&kl, g_kl);
    cudaGetSymbolAddress((void**)&vh, g_vh); cudaGetSymbolAddress((void**)&vl, g_vl);
    cudaGetSymbolAddress((void**)&ah, g_ah); cudaGetSymbolAddress((void**)&al, g_al);
    cudaGetSymbolAddress((void**)&fh, g_fh); cudaGetSymbolAddress((void**)&fl, g_fl);
    cudaGetSymbolAddress((void**)&wqh, g_wqh); cudaGetSymbolAddress((void**)&wql, g_wql);
    cudaGetSymbolAddress((void**)&wkh, g_wkh); cudaGetSymbolAddress((void**)&wkl, g_wkl);
    cudaGetSymbolAddress((void**)&wvh, g_wvh); cudaGetSymbolAddress((void**)&wvl, g_wvl);
    cudaGetSymbolAddress((void**)&woh, g_woh); cudaGetSymbolAddress((void**)&wol, g_wol);
    cudaGetSymbolAddress((void**)&w1h, g_w1h); cudaGetSymbolAddress((void**)&w1l, g_w1l);
    cudaGetSymbolAddress((void**)&w2h, g_w2h); cudaGetSymbolAddress((void**)&w2l, g_w2l);

    cudaFuncSetAttribute(attn_tc_kernel, cudaFuncAttributeMaxDynamicSharedMemorySize, ATTN_SMEM);
    cudaFuncSetAttribute(gemm_tc_kernel<0>, cudaFuncAttributeMaxDynamicSharedMemorySize, GEMM_SMEM);
    cudaFuncSetAttribute(gemm_tc_kernel<1>, cudaFuncAttributeMaxDynamicSharedMemorySize, GEMM_SMEM);
    cudaFuncSetAttribute(gemm_tc_kernel<2>, cudaFuncAttributeMaxDynamicSharedMemorySize, GEMM_SMEM);
    cudaFuncSetAttribute(gemm_qkv_kernel, cudaFuncAttributeMaxDynamicSharedMemorySize, GEMM_SMEM);

    split_kernel<<<NLAYER * EDIM * EDIM / 1024, 256>>>(Wq, wqh, wql);
    split_kernel<<<NLAYER * EDIM * EDIM / 1024, 256>>>(Wk, wkh, wkl);
    split_kernel<<<NLAYER * EDIM * EDIM / 1024, 256>>>(Wv, wvh, wvl);
    split_kernel<<<NLAYER * EDIM * EDIM / 1024, 256>>>(Wo, woh, wol);
    split_kernel<<<NLAYER * EDIM * FFDIM / 1024, 256>>>(W1, w1h, w1l);
    split_kernel<<<NLAYER * FFDIM * EDIM / 1024, 256>>>(W2, w2h, w2l);

    embed_kernel<<<(NTOK * EDIM) / 256, 256>>>(x, emb, pos, h32, hh, hl);

    dim3 gE(EDIM / BN, NTOK / BM);
    dim3 gQKV(EDIM / BN, NTOK / BM, 3);
    dim3 gF(FFDIM / BN, NTOK / BM);

    for (int l = 0; l < NLAYER; l++) {
        size_t wo_off = (size_t)l * EDIM * EDIM;
        size_t w1_off = (size_t)l * EDIM * FFDIM;
        size_t w2_off = (size_t)l * FFDIM * EDIM;

        gemm_qkv_kernel<<<gQKV, 128, GEMM_SMEM>>>(
            hh, hl,
            wqh + wo_off, wql + wo_off, wkh + wo_off, wkl + wo_off,
            wvh + wo_off, wvl + wo_off,
            bq + l * EDIM, bk + l * EDIM, bv + l * EDIM,
            qh, ql, kh, kl, vh, vl);

        attn_tc_kernel<<<dim3(SEQ / QT, NB * HEADS), 256, ATTN_SMEM>>>(
            qh, ql, kh, kl, vh, vl, mask, ah, al);

        gemm_tc_kernel<0><<<gE, 128, GEMM_SMEM>>>(
            ah, al, woh + wo_off, wol + wo_off, bo + l * EDIM, p32, nullptr, nullptr,
            EDIM, EDIM);
        ln_kernel<true><<<NTOK, 128>>>(p32, h32, g1 + l * EDIM, be1 + l * EDIM, h32, hh, hl);

        gemm_tc_kernel<2><<<gF, 128, GEMM_SMEM>>>(
            hh, hl, w1h + w1_off, w1l + w1_off, bf1 + l * FFDIM, nullptr, fh, fl,
            EDIM, FFDIM);
        gemm_tc_kernel<0><<<gE, 128, GEMM_SMEM>>>(
            fh, fl, w2h + w2_off, w2l + w2_off, bf2 + l * EDIM, p32, nullptr, nullptr,
            FFDIM, EDIM);

        if (l == NLAYER - 1)
            ln_kernel<false><<<NTOK, 128>>>(p32, h32, g2 + l * EDIM, be2 + l * EDIM,
                                            outp, nullptr, nullptr);
        else
            ln_kernel<true><<<NTOK, 128>>>(p32, h32, g2 + l * EDIM, be2 + l * EDIM,
                                           h32, hh, hl);
    }
}

// round 14
// speedup vs baseline: 1.1983x; 1.0833x over previous
#include <cuda_runtime.h>
#include <cuda_bf16.h>
#include <mma.h>
#include <math.h>
#include <stdint.h>

using namespace nvcuda;

#define NTOK 8192
#define EDIM 512
#define SEQ  2048
#define NB   4
#define HEADS 8
#define HD   64
#define FFDIM 2048
#define NLAYER 2

typedef __nv_bfloat16 bf16;
typedef __nv_bfloat162 bf162;

// ---------------- scratch (device globals; no allocation) ----------------
__device__ float g_h32[NTOK * EDIM];
__device__ float g_p32[NTOK * EDIM];
__device__ bf16 g_hh[NTOK * EDIM], g_hl[NTOK * EDIM];
__device__ bf16 g_qh[NTOK * EDIM], g_ql[NTOK * EDIM];
__device__ bf16 g_kh[NTOK * EDIM], g_kl[NTOK * EDIM];
__device__ bf16 g_vh[NTOK * EDIM], g_vl[NTOK * EDIM];
__device__ bf16 g_ah[NTOK * EDIM], g_al[NTOK * EDIM];
__device__ bf16 g_fh[NTOK * FFDIM], g_fl[NTOK * FFDIM];
__device__ bf16 g_wqh[NLAYER * EDIM * EDIM], g_wql[NLAYER * EDIM * EDIM];
__device__ bf16 g_wkh[NLAYER * EDIM * EDIM], g_wkl[NLAYER * EDIM * EDIM];
__device__ bf16 g_wvh[NLAYER * EDIM * EDIM], g_wvl[NLAYER * EDIM * EDIM];
__device__ bf16 g_woh[NLAYER * EDIM * EDIM], g_wol[NLAYER * EDIM * EDIM];
__device__ bf16 g_w1h[NLAYER * EDIM * FFDIM], g_w1l[NLAYER * EDIM * FFDIM];
__device__ bf16 g_w2h[NLAYER * FFDIM * EDIM], g_w2l[NLAYER * FFDIM * EDIM];

__device__ __forceinline__ void split1(float x, bf16& h, bf16& l) {
    h = __float2bfloat16(x);
    l = __float2bfloat16(x - __bfloat162float(h));
}

__device__ __forceinline__ void cp_async16(void* smem, const void* gmem) {
    unsigned int s = (unsigned int)__cvta_generic_to_shared(smem);
    asm volatile("cp.async.cg.shared.global [%0], [%1], 16;\n" :: "r"(s), "l"(gmem));
}
__device__ __forceinline__ void cp_commit() {
    asm volatile("cp.async.commit_group;\n");
}
template <int N>
__device__ __forceinline__ void cp_wait() {
    asm volatile("cp.async.wait_group %0;\n" :: "n"(N));
}

// ---------------- weight pre-split ----------------
__global__ void split_kernel(const float* __restrict__ src, bf16* __restrict__ hi,
                             bf16* __restrict__ lo) {
    int i = (blockIdx.x * 256 + threadIdx.x) * 4;
    float4 v = *(const float4*)(src + i);
    bf16 h0, l0, h1, l1, h2, l2, h3, l3;
    split1(v.x, h0, l0); split1(v.y, h1, l1);
    split1(v.z, h2, l2); split1(v.w, h3, l3);
    *(bf162*)(hi + i)     = bf162(h0, h1);
    *(bf162*)(hi + i + 2) = bf162(h2, h3);
    *(bf162*)(lo + i)     = bf162(l0, l1);
    *(bf162*)(lo + i + 2) = bf162(l2, l3);
}

// ---------------- embedding + positional (fp32 + split) ----------------
__global__ void embed_kernel(const int* __restrict__ x,
                             const float* __restrict__ emb,
                             const float* __restrict__ pos,
                             float* __restrict__ h,
                             bf16* __restrict__ hh, bf16* __restrict__ hl) {
    int idx = blockIdx.x * blockDim.x + threadIdx.x;
    int n = idx >> 9;
    int e = idx & 511;
    int tok = x[n] + 1;
    int s = n & (SEQ - 1);
    float v = emb[tok * EDIM + e] + pos[s * EDIM + e];
    h[idx] = v;
    bf16 hv, lv;
    split1(v, hv, lv);
    hh[idx] = hv;
    hl[idx] = lv;
}

// ---------------- bf16x3 tensor-core GEMM ----------------
#define BM 128
#define BN 128
#define BK 32
#define SA_STR 56
#define SB_STR 136
#define EPI_STR 68
#define ABUFH (BM * SA_STR)
#define STG_A (2 * ABUFH)
#define BBUFH (BK * SB_STR)
#define STG_B (2 * BBUFH)
#define STG_ELEMS (STG_A + STG_B)
#define NSTAGE 2
#define GEMM_SMEM (NSTAGE * STG_ELEMS * 2)   // 92160 bytes

__device__ __forceinline__
void gemm_load_stage(const bf16* Ah, const bf16* Al, const bf16* Wh, const bf16* Wl,
                     int K, int M, int rowBase, int colBase, int k0,
                     bf16* st, int tid) {
    bf16* sAh = st;
    bf16* sAl = st + ABUFH;
    bf16* sBh = st + STG_A;
    bf16* sBl = st + STG_A + BBUFH;
    #pragma unroll
    for (int i = 0; i < 4; i++) {
        int f = tid + i * 128;
        int r = f >> 2, c = (f & 3) * 8;
        cp_async16(&sAh[r * SA_STR + c], Ah + (size_t)(rowBase + r) * K + k0 + c);
        cp_async16(&sAl[r * SA_STR + c], Al + (size_t)(rowBase + r) * K + k0 + c);
        int rB = f >> 4, cB = (f & 15) * 8;
        cp_async16(&sBh[rB * SB_STR + cB], Wh + (size_t)(k0 + rB) * M + colBase + cB);
        cp_async16(&sBl[rB * SB_STR + cB], Wl + (size_t)(k0 + rB) * M + colBase + cB);
    }
}

// MODE: 0 = fp32 out, 1 = split out, 2 = split + relu out, 3 = fp32 + residual
template <int MODE>
__device__ __forceinline__
void gemm_body(const bf16* Ah, const bf16* Al, const bf16* Wh, const bf16* Wl,
               const float* __restrict__ bias, const float* __restrict__ resid,
               float* C, bf16* Chi, bf16* Clo,
               int K, int M, int rowBase, int colBase, char* dynsmem) {
    bf16* base = (bf16*)dynsmem;
    int tid = threadIdx.x;
    int lane = tid & 31;
    int wid = tid >> 5;
    int wm = wid & 1;
    int wn = wid >> 1;
    int nk = K / BK;

    wmma::fragment<wmma::accumulator, 16, 16, 16, float> acc[4][4];
    #pragma unroll
    for (int i = 0; i < 4; i++)
        #pragma unroll
        for (int j = 0; j < 4; j++)
            wmma::fill_fragment(acc[i][j], 0.0f);

    gemm_load_stage(Ah, Al, Wh, Wl, K, M, rowBase, colBase, 0, base, tid);
    cp_commit();
    gemm_load_stage(Ah, Al, Wh, Wl, K, M, rowBase, colBase, BK, base + STG_ELEMS, tid);
    cp_commit();

    for (int kc = 0; kc < nk; kc++) {
        cp_wait<1>();
        __syncthreads();

        bf16* st = base + (kc & 1) * STG_ELEMS;
        bf16* sAh = st;
        bf16* sAl = st + ABUFH;
        bf16* sBh = st + STG_A;
        bf16* sBl = st + STG_A + BBUFH;
        #pragma unroll
        for (int ks = 0; ks < BK; ks += 16) {
            wmma::fragment<wmma::matrix_a, 16, 16, 16, bf16, wmma::row_major> ah[4], al[4];
            wmma::fragment<wmma::matrix_b, 16, 16, 16, bf16, wmma::row_major> bh[4], bl[4];
            #pragma unroll
            for (int i = 0; i < 4; i++)
                wmma::load_matrix_sync(ah[i], &sAh[(wm * 64 + i * 16) * SA_STR + ks], SA_STR);
            #pragma unroll
            for (int j = 0; j < 4; j++)
                wmma::load_matrix_sync(bh[j], &sBh[ks * SB_STR + wn * 64 + j * 16], SB_STR);
            #pragma unroll
            for (int i = 0; i < 4; i++)
                #pragma unroll
                for (int j = 0; j < 4; j++)
                    wmma::mma_sync(acc[i][j], ah[i], bh[j], acc[i][j]);
            #pragma unroll
            for (int j = 0; j < 4; j++)
                wmma::load_matrix_sync(bl[j], &sBl[ks * SB_STR + wn * 64 + j * 16], SB_STR);
            #pragma unroll
            for (int i = 0; i < 4; i++)
                #pragma unroll
                for (int j = 0; j < 4; j++)
                    wmma::mma_sync(acc[i][j], ah[i], bl[j], acc[i][j]);
            #pragma unroll
            for (int i = 0; i < 4; i++)
                wmma::load_matrix_sync(al[i], &sAl[(wm * 64 + i * 16) * SA_STR + ks], SA_STR);
            #pragma unroll
            for (int i = 0; i < 4; i++)
                #pragma unroll
                for (int j = 0; j < 4; j++)
                    wmma::mma_sync(acc[i][j], al[i], bh[j], acc[i][j]);
        }
        __syncthreads();

        if (kc + 2 < nk)
            gemm_load_stage(Ah, Al, Wh, Wl, K, M, rowBase, colBase, (kc + 2) * BK,
                            base + (kc & 1) * STG_ELEMS, tid);
        cp_commit();
    }

    cp_wait<0>();
    __syncthreads();

    float* stg = (float*)dynsmem + wid * (64 * EPI_STR);
    #pragma unroll
    for (int i = 0; i < 4; i++)
        #pragma unroll
        for (int j = 0; j < 4; j++)
            wmma::store_matrix_sync(stg + i * 16 * EPI_STR + j * 16, acc[i][j],
                                    EPI_STR, wmma::mem_row_major);
    __syncwarp();

    int rowW = rowBase + wm * 64;
    int colW = colBase + wn * 64;
    #pragma unroll
    for (int it = 0; it < 32; it++) {
        int f = it * 32 + lane;
        int r = f >> 4;
        int c4 = (f & 15) << 2;
        float4 v = *(float4*)(stg + r * EPI_STR + c4);
        float4 bb = *(const float4*)(bias + colW + c4);
        v.x += bb.x; v.y += bb.y; v.z += bb.z; v.w += bb.w;
        if (MODE == 3) {
            float4 rr4 = *(const float4*)(resid + (size_t)(rowW + r) * M + colW + c4);
            v.x += rr4.x; v.y += rr4.y; v.z += rr4.z; v.w += rr4.w;
        }
        if (MODE == 2) {
            v.x = fmaxf(v.x, 0.f); v.y = fmaxf(v.y, 0.f);
            v.z = fmaxf(v.z, 0.f); v.w = fmaxf(v.w, 0.f);
        }
        if (MODE == 0 || MODE == 3) {
            *(float4*)(C + (size_t)(rowW + r) * M + colW + c4) = v;
        } else {
            bf16 h0, l0, h1, l1, h2, l2, h3, l3;
            split1(v.x, h0, l0); split1(v.y, h1, l1);
            split1(v.z, h2, l2); split1(v.w, h3, l3);
            size_t off = (size_t)(rowW + r) * M + colW + c4;
            *(bf162*)(Chi + off)     = bf162(h0, h1);
            *(bf162*)(Chi + off + 2) = bf162(h2, h3);
            *(bf162*)(Clo + off)     = bf162(l0, l1);
            *(bf162*)(Clo + off + 2) = bf162(l2, l3);
        }
    }
}

template <int MODE>
__global__ __launch_bounds__(128, 2)
void gemm_tc_kernel(const bf16* Ah, const bf16* Al, const bf16* Wh, const bf16* Wl,
                    const float* __restrict__ bias, const float* __restrict__ resid,
                    float* C, bf16* Chi, bf16* Clo, int K, int M) {
    extern __shared__ char dynsmem[];
    gemm_body<MODE>(Ah, Al, Wh, Wl, bias, resid, C, Chi, Clo, K, M,
                    blockIdx.y * BM, blockIdx.x * BN, dynsmem);
}

__global__ __launch_bounds__(128, 2)
void gemm_qkv_kernel(const bf16* Ah, const bf16* Al,
                     const bf16* Wqh, const bf16* Wql, const bf16* Wkh, const bf16* Wkl,
                     const bf16* Wvh, const bf16* Wvl,
                     const float* bq, const float* bk, const float* bv,
                     bf16* qh, bf16* ql, bf16* kh, bf16* kl, bf16* vh, bf16* vl) {
    extern __shared__ char dynsmem[];
    const bf16 *Wh, *Wl;
    const float* bias;
    bf16 *Chi, *Clo;
    if (blockIdx.z == 0)      { Wh = Wqh; Wl = Wql; bias = bq; Chi = qh; Clo = ql; }
    else if (blockIdx.z == 1) { Wh = Wkh; Wl = Wkl; bias = bk; Chi = kh; Clo = kl; }
    else                      { Wh = Wvh; Wl = Wvl; bias = bv; Chi = vh; Clo = vl; }
    gemm_body<1>(Ah, Al, Wh, Wl, bias, nullptr, nullptr, Chi, Clo, EDIM, EDIM,
                 blockIdx.y * BM, blockIdx.x * BN, dynsmem);
}

// ---------------- tensor-core flash attention: 128-query tile, P/S alias
// P hi-only; V hi-only (P*V = Ph*Vh, errors cancel across keys).
#define QT 128
#define KSTR 72
#define SSTR 68
#define PSTR 136
#define AQH 0
#define AQL (QT * KSTR)
#define AKH (2 * QT * KSTR)
#define AKL (AKH + 64 * KSTR)
#define AVH (AKH + 2 * 64 * KSTR)
#define PH_OFF (AKH + 3 * 64 * KSTR)
#define SF_OFF (PH_OFF * 2)                   // 64512 bytes
#define ATTN_SMEM (SF_OFF + QT * SSTR * 4)    // 99328 bytes

__device__ __forceinline__
void attn_load_k(const bf16* gh, const bf16* gl, bf16* sb,
                 size_t rowG, int colB, int tid) {
    #pragma unroll
    for (int i = 0; i < 2; i++) {
        int f = tid + i * 256;
        int r = f >> 3, c = (f & 7) * 8;
        cp_async16(&sb[AKH + r * KSTR + c], gh + (rowG + r) * EDIM + colB + c);
        cp_async16(&sb[AKL + r * KSTR + c], gl + (rowG + r) * EDIM + colB + c);
    }
}
__device__ __forceinline__
void attn_load_v(const bf16* gh, bf16* sb, size_t rowG, int colB, int tid) {
    #pragma unroll
    for (int i = 0; i < 2; i++) {
        int f = tid + i * 256;
        int r = f >> 3, c = (f & 7) * 8;
        cp_async16(&sb[AVH + r * KSTR + c], gh + (rowG + r) * EDIM + colB + c);
    }
}

__global__ __launch_bounds__(256, 2)
void attn_tc_kernel(const bf16* __restrict__ qh, const bf16* __restrict__ ql,
                    const bf16* __restrict__ kh, const bf16* __restrict__ kl,
                    const bf16* __restrict__ vh,
                    const int* __restrict__ mask,
                    bf16* __restrict__ oh, bf16* __restrict__ ol) {
    extern __shared__ char smraw[];
    bf16* sb = (bf16*)smraw;
    float* Sf = (float*)(smraw + SF_OFF);

    int tid = threadIdx.x;
    int wid = tid >> 5;
    int wr = (wid & 3) * 32;
    int wc = (wid >> 2) * 32;
    int b  = blockIdx.y >> 3;
    int hh = blockIdx.y & 7;
    int q0 = blockIdx.x * QT;
    int colB = hh * HD;
    size_t qrow = (size_t)(b * SEQ + q0);
    size_t krow = (size_t)(b * SEQ);

    {
        bf162 sc = __float2bfloat162_rn(0.125f);
        #pragma unroll
        for (int i = 0; i < 4; i++) {
            int f = tid + i * 256;
            int r = f >> 3, c = (f & 7) * 8;
            uint4 uh = *(const uint4*)(qh + (qrow + r) * EDIM + colB + c);
            uint4 ulo = *(const uint4*)(ql + (qrow + r) * EDIM + colB + c);
            bf162* ph = (bf162*)&uh;
            bf162* pl = (bf162*)&ulo;
            #pragma unroll
            for (int j = 0; j < 4; j++) { ph[j] = __hmul2(ph[j], sc); pl[j] = __hmul2(pl[j], sc); }
            *(uint4*)&sb[AQH + r * KSTR + c] = uh;
            *(uint4*)&sb[AQL + r * KSTR + c] = ulo;
        }
    }

    int rr = tid >> 1;
    int pp = tid & 1;
    float o_acc[32];
    #pragma unroll
    for (int i = 0; i < 32; i++) o_acc[i] = 0.f;
    float mrun = -1e30f, lrun = 0.f;

    attn_load_k(kh, kl, sb, krow, colB, tid);
    attn_load_v(vh, sb, krow, colB, tid);
    cp_commit();

    for (int kb = 0; kb < SEQ / 64; kb++) {
        cp_wait<0>();
        __syncthreads();

        // S = Q @ K^T (128x64x64), bf16x3
        {
            wmma::fragment<wmma::matrix_a, 16, 16, 16, bf16, wmma::row_major> qa_h[2], qa_l[2];
            wmma::fragment<wmma::matrix_b, 16, 16, 16, bf16, wmma::col_major> kb_h[2], kb_l[2];
            wmma::fragment<wmma::accumulator, 16, 16, 16, float> sacc[2][2];
            #pragma unroll
            for (int i = 0; i < 2; i++)
                #pragma unroll
                for (int j = 0; j < 2; j++)
                    wmma::fill_fragment(sacc[i][j], 0.f);
            #pragma unroll
            for (int kk = 0; kk < 4; kk++) {
                #pragma unroll
                for (int i = 0; i < 2; i++) {
                    wmma::load_matrix_sync(qa_h[i], &sb[AQH + (wr + i * 16) * KSTR + kk * 16], KSTR);
                    wmma::load_matrix_sync(qa_l[i], &sb[AQL + (wr + i * 16) * KSTR + kk * 16], KSTR);
                }
                #pragma unroll
                for (int j = 0; j < 2; j++) {
                    wmma::load_matrix_sync(kb_h[j], &sb[AKH + (wc + j * 16) * KSTR + kk * 16], KSTR);
                    wmma::load_matrix_sync(kb_l[j], &sb[AKL + (wc + j * 16) * KSTR + kk * 16], KSTR);
                }
                #pragma unroll
                for (int i = 0; i < 2; i++)
                    #pragma unroll
                    for (int j = 0; j < 2; j++) {
                        wmma::mma_sync(sacc[i][j], qa_h[i], kb_h[j], sacc[i][j]);
                        wmma::mma_sync(sacc[i][j], qa_h[i], kb_l[j], sacc[i][j]);
                        wmma::mma_sync(sacc[i][j], qa_l[i], kb_h[j], sacc[i][j]);
                    }
            }
            #pragma unroll
            for (int i = 0; i < 2; i++)
                #pragma unroll
                for (int j = 0; j < 2; j++)
                    wmma::store_matrix_sync(&Sf[(wr + i * 16) * SSTR + wc + j * 16],
                                            sacc[i][j], SSTR, wmma::mem_row_major);
        }
        __syncthreads();

        if (kb + 1 < SEQ / 64)
            attn_load_k(kh, kl, sb, krow + (kb + 1) * 64, colB, tid);
        cp_commit();

        // softmax: 2 threads/row; P stored hi-only
        {
            const float* srow = &Sf[rr * SSTR + pp * 32];
            const int4* mrow = (const int4*)(mask + b * SEQ + kb * 64 + pp * 32);
            float s[32];
            #pragma unroll
            for (int i = 0; i < 8; i++) {
                float4 sv = *(const float4*)(srow + i * 4);
                int4 mk = mrow[i];
                s[4 * i + 0] = mk.x ? sv.x : -1e20f;
                s[4 * i + 1] = mk.y ? sv.y : -1e20f;
                s[4 * i + 2] = mk.z ? sv.z : -1e20f;
                s[4 * i + 3] = mk.w ? sv.w : -1e20f;
            }
            __syncwarp();
            float mloc = s[0];
            #pragma unroll
            for (int i = 1; i < 32; i++) mloc = fmaxf(mloc, s[i]);
            mloc = fmaxf(mloc, __shfl_xor_sync(0xffffffffu, mloc, 1));
            float mnew = fmaxf(mrun, mloc);
            float corr = __expf(mrun - mnew);
            mrun = mnew;
            float psum = 0.f;
            bf162* ph = (bf162*)&sb[PH_OFF + rr * PSTR + pp * 32];
            #pragma unroll
            for (int i = 0; i < 16; i++) {
                float p0 = __expf(s[2 * i] - mnew);
                float p1 = __expf(s[2 * i + 1] - mnew);
                psum += p0 + p1;
                ph[i] = bf162(__float2bfloat16(p0), __float2bfloat16(p1));
            }
            psum += __shfl_xor_sync(0xffffffffu, psum, 1);
            lrun = lrun * corr + psum;
            #pragma unroll
            for (int i = 0; i < 32; i++) o_acc[i] *= corr;
        }
        __syncthreads();

        // Opart = Ph @ Vh (single term)
        {
            wmma::fragment<wmma::matrix_a, 16, 16, 16, bf16, wmma::row_major> pa_h[2];
            wmma::fragment<wmma::matrix_b, 16, 16, 16, bf16, wmma::row_major> vb_h[2];
            wmma::fragment<wmma::accumulator, 16, 16, 16, float> oacc[2][2];
            #pragma unroll
            for (int i = 0; i < 2; i++)
                #pragma unroll
                for (int j = 0; j < 2; j++)
                    wmma::fill_fragment(oacc[i][j], 0.f);
            #pragma unroll
            for (int kk = 0; kk < 4; kk++) {
                #pragma unroll
                for (int i = 0; i < 2; i++)
                    wmma::load_matrix_sync(pa_h[i], &sb[PH_OFF + (wr + i * 16) * PSTR + kk * 16], PSTR);
                #pragma unroll
                for (int j = 0; j < 2; j++)
                    wmma::load_matrix_sync(vb_h[j], &sb[AVH + (kk * 16) * KSTR + wc + j * 16], KSTR);
                #pragma unroll
                for (int i = 0; i < 2; i++)
                    #pragma unroll
                    for (int j = 0; j < 2; j++)
                        wmma::mma_sync(oacc[i][j], pa_h[i], vb_h[j], oacc[i][j]);
            }
            __syncthreads();
            #pragma unroll
            for (int i = 0; i < 2; i++)
                #pragma unroll
                for (int j = 0; j < 2; j++)
                    wmma::store_matrix_sync(&Sf[(wr + i * 16) * SSTR + wc + j * 16],
                                            oacc[i][j], SSTR, wmma::mem_row_major);
        }
        __syncthreads();

        if (kb + 1 < SEQ / 64)
            attn_load_v(vh, sb, krow + (kb + 1) * 64, colB, tid);
        cp_commit();

        {
            const float* orow = &Sf[rr * SSTR + pp * 32];
            #pragma unroll
            for (int i = 0; i < 8; i++) {
                float4 op = *(const float4*)(orow + i * 4);
                o_acc[4 * i + 0] += op.x;
                o_acc[4 * i + 1] += op.y;
                o_acc[4 * i + 2] += op.z;
                o_acc[4 * i + 3] += op.w;
            }
        }
    }

    float inv = 1.f / lrun;
    size_t obase = (qrow + rr) * EDIM + colB + pp * 32;
    #pragma unroll
    for (int i = 0; i < 16; i++) {
        float v0 = o_acc[2 * i] * inv;
        float v1 = o_acc[2 * i + 1] * inv;
        bf16 h0, l0, h1, l1;
        split1(v0, h0, l0); split1(v1, h1, l1);
        *(bf162*)(oh + obase + 2 * i) = bf162(h0, h1);
        *(bf162*)(ol + obase + 2 * i) = bf162(l0, l1);
    }
}

// ---------------- LayerNorm on pre-summed input (fp32 + optional split) --
template <bool SPLIT>
__global__ __launch_bounds__(128)
void ln_kernel(const float* __restrict__ A,
               const float* __restrict__ g, const float* __restrict__ be,
               float* __restrict__ out, bf16* __restrict__ ohi, bf16* __restrict__ olo) {
    __shared__ float red[4];
    int n = blockIdx.x;
    int t = threadIdx.x;
    float4 a = ((const float4*)(A + (size_t)n * EDIM))[t];
    float v[4] = {a.x, a.y, a.z, a.w};

    float s = v[0] + v[1] + v[2] + v[3];
    #pragma unroll
    for (int o = 16; o; o >>= 1) s += __shfl_xor_sync(0xffffffffu, s, o);
    if ((t & 31) == 0) red[t >> 5] = s;
    __syncthreads();
    float mu = (red[0] + red[1] + red[2] + red[3]) * (1.f / EDIM);
    __syncthreads();

    v[0] -= mu; v[1] -= mu; v[2] -= mu; v[3] -= mu;
    float sq = v[0] * v[0] + v[1] * v[1] + v[2] * v[2] + v[3] * v[3];
    #pragma unroll
    for (int o = 16; o; o >>= 1) sq += __shfl_xor_sync(0xffffffffu, sq, o);
    if ((t & 31) == 0) red[t >> 5] = sq;
    __syncthreads();
    float var = (red[0] + red[1] + red[2] + red[3]) * (1.f / EDIM);
    float rs = rsqrtf(var + 1e-6f);

    float4 gg = ((const float4*)g)[t];
    float4 bb = ((const float4*)be)[t];
    float o0 = v[0] * rs * gg.x + bb.x;
    float o1 = v[1] * rs * gg.y + bb.y;
    float o2 = v[2] * rs * gg.z + bb.z;
    float o3 = v[3] * rs * gg.w + bb.w;
    float4 o = {o0, o1, o2, o3};
    ((float4*)(out + (size_t)n * EDIM))[t] = o;
    if (SPLIT) {
        bf16 h0, l0, h1, l1, h2, l2, h3, l3;
        split1(o0, h0, l0); split1(o1, h1, l1);
        split1(o2, h2, l2); split1(o3, h3, l3);
        size_t off = (size_t)n * EDIM + t * 4;
        *(bf162*)(ohi + off)     = bf162(h0, h1);
        *(bf162*)(ohi + off + 2) = bf162(h2, h3);
        *(bf162*)(olo + off)     = bf162(l0, l1);
        *(bf162*)(olo + off + 2) = bf162(l2, l3);
    }
}

// ---------------- launcher ----------------
extern "C" void kernel_launch(void* const* d_in, const int* in_sizes, int n_in,
                              void* d_out, int out_size) {
    const int*   x    = (const int*)  d_in[0];
    const int*   mask = (const int*)  d_in[1];
    const float* emb  = (const float*)d_in[2];
    const float* pos  = (const float*)d_in[3];
    const float* Wq   = (const float*)d_in[4];
    const float* bq   = (const float*)d_in[5];
    const float* Wk   = (const float*)d_in[6];
    const float* bk   = (const float*)d_in[7];
    const float* Wv   = (const float*)d_in[8];
    const float* bv   = (const float*)d_in[9];
    const float* Wo   = (const float*)d_in[10];
    const float* bo   = (const float*)d_in[11];
    const float* g1   = (const float*)d_in[12];
    const float* be1  = (const float*)d_in[13];
    const float* g2   = (const float*)d_in[14];
    const float* be2  = (const float*)d_in[15];
    const float* W1   = (const float*)d_in[16];
    const float* bf1  = (const float*)d_in[17];
    const float* W2   = (const float*)d_in[18];
    const float* bf2  = (const float*)d_in[19];
    float* outp = (float*)d_out;

    float *h32, *p32;
    bf16 *hh, *hl, *qh, *ql, *kh, *kl, *vh, *vl, *ah, *al, *fh, *fl;
    bf16 *wqh, *wql, *wkh, *wkl, *wvh, *wvl, *woh, *wol, *w1h, *w1l, *w2h, *w2l;
    cudaGetSymbolAddress((void**)&h32, g_h32);
    cudaGetSymbolAddress((void**)&p32, g_p32);
    cudaGetSymbolAddress((void**)&hh, g_hh); cudaGetSymbolAddress((void**)&hl, g_hl);
    cudaGetSymbolAddress((void**)&qh, g_qh); cudaGetSymbolAddress((void**)&ql, g_ql);
    cudaGetSymbolAddress((void**)&kh, g_kh); cudaGetSymbolAddress((void**)&kl, g_kl);
    cudaGetSymbolAddress((void**)&vh, g_vh); cudaGetSymbolAddress((void**)&vl, g_vl);
    cudaGetSymbolAddress((void**)&ah, g_ah); cudaGetSymbolAddress((void**)&al, g_al);
    cudaGetSymbolAddress((void**)&fh, g_fh); cudaGetSymbolAddress((void**)&fl, g_fl);
    cudaGetSymbolAddress((void**)&wqh, g_wqh); cudaGetSymbolAddress((void**)&wql, g_wql);
    cudaGetSymbolAddress((void**)&wkh, g_wkh); cudaGetSymbolAddress((void**)&wkl, g_wkl);
    cudaGetSymbolAddress((void**)&wvh, g_wvh); cudaGetSymbolAddress((void**)&wvl, g_wvl);
    cudaGetSymbolAddress((void**)&woh, g_woh); cudaGetSymbolAddress((void**)&wol, g_wol);
    cudaGetSymbolAddress((void**)&w1h, g_w1h); cudaGetSymbolAddress((void**)&w1l, g_w1l);
    cudaGetSymbolAddress((void**)&w2h, g_w2h); cudaGetSymbolAddress((void**)&w2l, g_w2l);

    cudaFuncSetAttribute(attn_tc_kernel, cudaFuncAttributeMaxDynamicSharedMemorySize, ATTN_SMEM);
    cudaFuncSetAttribute(gemm_tc_kernel<1>, cudaFuncAttributeMaxDynamicSharedMemorySize, GEMM_SMEM);
    cudaFuncSetAttribute(gemm_tc_kernel<2>, cudaFuncAttributeMaxDynamicSharedMemorySize, GEMM_SMEM);
    cudaFuncSetAttribute(gemm_tc_kernel<3>, cudaFuncAttributeMaxDynamicSharedMemorySize, GEMM_SMEM);
    cudaFuncSetAttribute(gemm_qkv_kernel, cudaFuncAttributeMaxDynamicSharedMemorySize, GEMM_SMEM);

    split_kernel<<<NLAYER * EDIM * EDIM / 1024, 256>>>(Wq, wqh, wql);
    split_kernel<<<NLAYER * EDIM * EDIM / 1024, 256>>>(Wk, wkh, wkl);
    split_kernel<<<NLAYER * EDIM * EDIM / 1024, 256>>>(Wv, wvh, wvl);
    split_kernel<<<NLAYER * EDIM * EDIM / 1024, 256>>>(Wo, woh, wol);
    split_kernel<<<NLAYER * EDIM * FFDIM / 1024, 256>>>(W1, w1h, w1l);
    split_kernel<<<NLAYER * FFDIM * EDIM / 1024, 256>>>(W2, w2h, w2l);

    embed_kernel<<<(NTOK * EDIM) / 256, 256>>>(x, emb, pos, h32, hh, hl);

    dim3 gE(EDIM / BN, NTOK / BM);
    dim3 gQKV(EDIM / BN, NTOK / BM, 3);
    dim3 gF(FFDIM / BN, NTOK / BM);

    for (int l = 0; l < NLAYER; l++) {
        size_t wo_off = (size_t)l * EDIM * EDIM;
        size_t w1_off = (size_t)l * EDIM * FFDIM;
        size_t w2_off = (size_t)l * FFDIM * EDIM;

        gemm_qkv_kernel<<<gQKV, 128, GEMM_SMEM>>>(
            hh, hl,
            wqh + wo_off, wql + wo_off, wkh + wo_off, wkl + wo_off,
            wvh + wo_off, wvl + wo_off,
            bq + l * EDIM, bk + l * EDIM, bv + l * EDIM,
            qh, ql, kh, kl, vh, vl);

        attn_tc_kernel<<<dim3(SEQ / QT, NB * HEADS), 256, ATTN_SMEM>>>(
            qh, ql, kh, kl, vh, mask, ah, al);

        // p32 = attn @ Wo + bo + h32  (residual fused)
        gemm_tc_kernel<3><<<gE, 128, GEMM_SMEM>>>(
            ah, al, woh + wo_off, wol + wo_off, bo + l * EDIM, h32, p32, nullptr, nullptr,
            EDIM, EDIM);
        ln_kernel<true><<<NTOK, 128>>>(p32, g1 + l * EDIM, be1 + l * EDIM, h32, hh, hl);

        gemm_tc_kernel<2><<<gF, 128, GEMM_SMEM>>>(
            hh, hl, w1h + w1_off, w1l + w1_off, bf1 + l * FFDIM, nullptr, nullptr, fh, fl,
            EDIM, FFDIM);
        // p32 = ffn @ W2 + bf2 + h32  (residual fused)
        gemm_tc_kernel<3><<<gE, 128, GEMM_SMEM>>>(
            fh, fl, w2h + w2_off, w2l + w2_off, bf2 + l * EDIM, h32, p32, nullptr, nullptr,
            FFDIM, EDIM);

        if (l == NLAYER - 1)
            ln_kernel<false><<<NTOK, 128>>>(p32, g2 + l * EDIM, be2 + l * EDIM,
                                            outp, nullptr, nullptr);
        else
            ln_kernel<true><<<NTOK, 128>>>(p32, g2 + l * EDIM, be2 + l * EDIM,
                                           h32, hh, hl);
    }
}

// round 15
// speedup vs baseline: 1.1996x; 1.0011x over previous
#include <cuda_runtime.h>
#include <cuda_bf16.h>
#include <mma.h>
#include <math.h>
#include <stdint.h>

using namespace nvcuda;

#define NTOK 8192
#define EDIM 512
#define SEQ  2048
#define NB   4
#define HEADS 8
#define HD   64
#define FFDIM 2048
#define NLAYER 2

typedef __nv_bfloat16 bf16;
typedef __nv_bfloat162 bf162;

// ---------------- scratch (device globals; no allocation) ----------------
__device__ float g_h32[NTOK * EDIM];
__device__ float g_p32[NTOK * EDIM];
__device__ bf16 g_hh[NTOK * EDIM], g_hl[NTOK * EDIM];
__device__ bf16 g_qh[NTOK * EDIM], g_ql[NTOK * EDIM];
__device__ bf16 g_kh[NTOK * EDIM], g_kl[NTOK * EDIM];
__device__ bf16 g_vh[NTOK * EDIM], g_vl[NTOK * EDIM];
__device__ bf16 g_ah[NTOK * EDIM], g_al[NTOK * EDIM];
__device__ bf16 g_fh[NTOK * FFDIM], g_fl[NTOK * FFDIM];
__device__ bf16 g_wqh[NLAYER * EDIM * EDIM], g_wql[NLAYER * EDIM * EDIM];
__device__ bf16 g_wkh[NLAYER * EDIM * EDIM], g_wkl[NLAYER * EDIM * EDIM];
__device__ bf16 g_wvh[NLAYER * EDIM * EDIM], g_wvl[NLAYER * EDIM * EDIM];
__device__ bf16 g_woh[NLAYER * EDIM * EDIM], g_wol[NLAYER * EDIM * EDIM];
__device__ bf16 g_w1h[NLAYER * EDIM * FFDIM], g_w1l[NLAYER * EDIM * FFDIM];
__device__ bf16 g_w2h[NLAYER * FFDIM * EDIM], g_w2l[NLAYER * FFDIM * EDIM];

__device__ __forceinline__ void split1(float x, bf16& h, bf16& l) {
    h = __float2bfloat16(x);
    l = __float2bfloat16(x - __bfloat162float(h));
}

__device__ __forceinline__ void cp_async16(void* smem, const void* gmem) {
    unsigned int s = (unsigned int)__cvta_generic_to_shared(smem);
    asm volatile("cp.async.cg.shared.global [%0], [%1], 16;\n" :: "r"(s), "l"(gmem));
}
__device__ __forceinline__ void cp_commit() {
    asm volatile("cp.async.commit_group;\n");
}
template <int N>
__device__ __forceinline__ void cp_wait() {
    asm volatile("cp.async.wait_group %0;\n" :: "n"(N));
}

// ---------------- weight pre-split ----------------
__global__ void split_kernel(const float* __restrict__ src, bf16* __restrict__ hi,
                             bf16* __restrict__ lo) {
    int i = (blockIdx.x * 256 + threadIdx.x) * 4;
    float4 v = *(const float4*)(src + i);
    bf16 h0, l0, h1, l1, h2, l2, h3, l3;
    split1(v.x, h0, l0); split1(v.y, h1, l1);
    split1(v.z, h2, l2); split1(v.w, h3, l3);
    *(bf162*)(hi + i)     = bf162(h0, h1);
    *(bf162*)(hi + i + 2) = bf162(h2, h3);
    *(bf162*)(lo + i)     = bf162(l0, l1);
    *(bf162*)(lo + i + 2) = bf162(l2, l3);
}

// ---------------- embedding + positional (fp32 + split) ----------------
__global__ void embed_kernel(const int* __restrict__ x,
                             const float* __restrict__ emb,
                             const float* __restrict__ pos,
                             float* __restrict__ h,
                             bf16* __restrict__ hh, bf16* __restrict__ hl) {
    int idx = blockIdx.x * blockDim.x + threadIdx.x;
    int n = idx >> 9;
    int e = idx & 511;
    int tok = x[n] + 1;
    int s = n & (SEQ - 1);
    float v = emb[tok * EDIM + e] + pos[s * EDIM + e];
    h[idx] = v;
    bf16 hv, lv;
    split1(v, hv, lv);
    hh[idx] = hv;
    hl[idx] = lv;
}

// ---------------- bf16x3 tensor-core GEMM ----------------
#define BM 128
#define BN 128
#define BK 32
#define SA_STR 56
#define SB_STR 136
#define EPI_STR 68
#define ABUFH (BM * SA_STR)
#define STG_A (2 * ABUFH)
#define BBUFH (BK * SB_STR)
#define STG_B (2 * BBUFH)
#define STG_ELEMS (STG_A + STG_B)
#define NSTAGE 2
#define GEMM_SMEM (NSTAGE * STG_ELEMS * 2)   // 92160 bytes

__device__ __forceinline__
void gemm_load_stage(const bf16* Ah, const bf16* Al, const bf16* Wh, const bf16* Wl,
                     int K, int M, int rowBase, int colBase, int k0,
                     bf16* st, int tid) {
    bf16* sAh = st;
    bf16* sAl = st + ABUFH;
    bf16* sBh = st + STG_A;
    bf16* sBl = st + STG_A + BBUFH;
    #pragma unroll
    for (int i = 0; i < 4; i++) {
        int f = tid + i * 128;
        int r = f >> 2, c = (f & 3) * 8;
        cp_async16(&sAh[r * SA_STR + c], Ah + (size_t)(rowBase + r) * K + k0 + c);
        cp_async16(&sAl[r * SA_STR + c], Al + (size_t)(rowBase + r) * K + k0 + c);
        int rB = f >> 4, cB = (f & 15) * 8;
        cp_async16(&sBh[rB * SB_STR + cB], Wh + (size_t)(k0 + rB) * M + colBase + cB);
        cp_async16(&sBl[rB * SB_STR + cB], Wl + (size_t)(k0 + rB) * M + colBase + cB);
    }
}

// MODE: 0 = fp32 out, 1 = split out, 2 = split + relu out, 3 = fp32 + residual
template <int MODE>
__device__ __forceinline__
void gemm_body(const bf16* Ah, const bf16* Al, const bf16* Wh, const bf16* Wl,
               const float* __restrict__ bias, const float* __restrict__ resid,
               float* C, bf16* Chi, bf16* Clo,
               int K, int M, int rowBase, int colBase, char* dynsmem) {
    bf16* base = (bf16*)dynsmem;
    int tid = threadIdx.x;
    int lane = tid & 31;
    int wid = tid >> 5;
    int wm = wid & 1;
    int wn = wid >> 1;
    int nk = K / BK;

    wmma::fragment<wmma::accumulator, 16, 16, 16, float> acc[4][4];
    #pragma unroll
    for (int i = 0; i < 4; i++)
        #pragma unroll
        for (int j = 0; j < 4; j++)
            wmma::fill_fragment(acc[i][j], 0.0f);

    gemm_load_stage(Ah, Al, Wh, Wl, K, M, rowBase, colBase, 0, base, tid);
    cp_commit();
    gemm_load_stage(Ah, Al, Wh, Wl, K, M, rowBase, colBase, BK, base + STG_ELEMS, tid);
    cp_commit();

    for (int kc = 0; kc < nk; kc++) {
        cp_wait<1>();
        __syncthreads();

        bf16* st = base + (kc & 1) * STG_ELEMS;
        bf16* sAh = st;
        bf16* sAl = st + ABUFH;
        bf16* sBh = st + STG_A;
        bf16* sBl = st + STG_A + BBUFH;
        #pragma unroll
        for (int ks = 0; ks < BK; ks += 16) {
            wmma::fragment<wmma::matrix_a, 16, 16, 16, bf16, wmma::row_major> ah[4], al[4];
            wmma::fragment<wmma::matrix_b, 16, 16, 16, bf16, wmma::row_major> bh[4], bl[4];
            #pragma unroll
            for (int i = 0; i < 4; i++)
                wmma::load_matrix_sync(ah[i], &sAh[(wm * 64 + i * 16) * SA_STR + ks], SA_STR);
            #pragma unroll
            for (int j = 0; j < 4; j++)
                wmma::load_matrix_sync(bh[j], &sBh[ks * SB_STR + wn * 64 + j * 16], SB_STR);
            #pragma unroll
            for (int i = 0; i < 4; i++)
                #pragma unroll
                for (int j = 0; j < 4; j++)
                    wmma::mma_sync(acc[i][j], ah[i], bh[j], acc[i][j]);
            #pragma unroll
            for (int j = 0; j < 4; j++)
                wmma::load_matrix_sync(bl[j], &sBl[ks * SB_STR + wn * 64 + j * 16], SB_STR);
            #pragma unroll
            for (int i = 0; i < 4; i++)
                #pragma unroll
                for (int j = 0; j < 4; j++)
                    wmma::mma_sync(acc[i][j], ah[i], bl[j], acc[i][j]);
            #pragma unroll
            for (int i = 0; i < 4; i++)
                wmma::load_matrix_sync(al[i], &sAl[(wm * 64 + i * 16) * SA_STR + ks], SA_STR);
            #pragma unroll
            for (int i = 0; i < 4; i++)
                #pragma unroll
                for (int j = 0; j < 4; j++)
                    wmma::mma_sync(acc[i][j], al[i], bh[j], acc[i][j]);
        }
        __syncthreads();

        if (kc + 2 < nk)
            gemm_load_stage(Ah, Al, Wh, Wl, K, M, rowBase, colBase, (kc + 2) * BK,
                            base + (kc & 1) * STG_ELEMS, tid);
        cp_commit();
    }

    cp_wait<0>();
    __syncthreads();

    float* stg = (float*)dynsmem + wid * (64 * EPI_STR);
    #pragma unroll
    for (int i = 0; i < 4; i++)
        #pragma unroll
        for (int j = 0; j < 4; j++)
            wmma::store_matrix_sync(stg + i * 16 * EPI_STR + j * 16, acc[i][j],
                                    EPI_STR, wmma::mem_row_major);
    __syncwarp();

    int rowW = rowBase + wm * 64;
    int colW = colBase + wn * 64;
    #pragma unroll
    for (int it = 0; it < 32; it++) {
        int f = it * 32 + lane;
        int r = f >> 4;
        int c4 = (f & 15) << 2;
        float4 v = *(float4*)(stg + r * EPI_STR + c4);
        float4 bb = *(const float4*)(bias + colW + c4);
        v.x += bb.x; v.y += bb.y; v.z += bb.z; v.w += bb.w;
        if (MODE == 3) {
            float4 rr4 = *(const float4*)(resid + (size_t)(rowW + r) * M + colW + c4);
            v.x += rr4.x; v.y += rr4.y; v.z += rr4.z; v.w += rr4.w;
        }
        if (MODE == 2) {
            v.x = fmaxf(v.x, 0.f); v.y = fmaxf(v.y, 0.f);
            v.z = fmaxf(v.z, 0.f); v.w = fmaxf(v.w, 0.f);
        }
        if (MODE == 0 || MODE == 3) {
            *(float4*)(C + (size_t)(rowW + r) * M + colW + c4) = v;
        } else {
            bf16 h0, l0, h1, l1, h2, l2, h3, l3;
            split1(v.x, h0, l0); split1(v.y, h1, l1);
            split1(v.z, h2, l2); split1(v.w, h3, l3);
            size_t off = (size_t)(rowW + r) * M + colW + c4;
            *(bf162*)(Chi + off)     = bf162(h0, h1);
            *(bf162*)(Chi + off + 2) = bf162(h2, h3);
            *(bf162*)(Clo + off)     = bf162(l0, l1);
            *(bf162*)(Clo + off + 2) = bf162(l2, l3);
        }
    }
}

template <int MODE>
__global__ __launch_bounds__(128, 2)
void gemm_tc_kernel(const bf16* Ah, const bf16* Al, const bf16* Wh, const bf16* Wl,
                    const float* __restrict__ bias, const float* __restrict__ resid,
                    float* C, bf16* Chi, bf16* Clo, int K, int M) {
    extern __shared__ char dynsmem[];
    gemm_body<MODE>(Ah, Al, Wh, Wl, bias, resid, C, Chi, Clo, K, M,
                    blockIdx.y * BM, blockIdx.x * BN, dynsmem);
}

__global__ __launch_bounds__(128, 2)
void gemm_qkv_kernel(const bf16* Ah, const bf16* Al,
                     const bf16* Wqh, const bf16* Wql, const bf16* Wkh, const bf16* Wkl,
                     const bf16* Wvh, const bf16* Wvl,
                     const float* bq, const float* bk, const float* bv,
                     bf16* qh, bf16* ql, bf16* kh, bf16* kl, bf16* vh, bf16* vl) {
    extern __shared__ char dynsmem[];
    const bf16 *Wh, *Wl;
    const float* bias;
    bf16 *Chi, *Clo;
    if (blockIdx.z == 0)      { Wh = Wqh; Wl = Wql; bias = bq; Chi = qh; Clo = ql; }
    else if (blockIdx.z == 1) { Wh = Wkh; Wl = Wkl; bias = bk; Chi = kh; Clo = kl; }
    else                      { Wh = Wvh; Wl = Wvl; bias = bv; Chi = vh; Clo = vl; }
    gemm_body<1>(Ah, Al, Wh, Wl, bias, nullptr, nullptr, Chi, Clo, EDIM, EDIM,
                 blockIdx.y * BM, blockIdx.x * BN, dynsmem);
}

// ---------------- tensor-core flash attention: 128-query tile, P/S alias
// P hi-only; V hi-only (P*V = Ph*Vh, errors cancel across keys).
#define QT 128
#define KSTR 72
#define SSTR 68
#define PSTR 136
#define AQH 0
#define AQL (QT * KSTR)
#define AKH (2 * QT * KSTR)
#define AKL (AKH + 64 * KSTR)
#define AVH (AKH + 2 * 64 * KSTR)
#define PH_OFF (AKH + 3 * 64 * KSTR)
#define SF_OFF (PH_OFF * 2)                   // 64512 bytes
#define ATTN_SMEM (SF_OFF + QT * SSTR * 4)    // 99328 bytes

__device__ __forceinline__
void attn_load_k(const bf16* gh, const bf16* gl, bf16* sb,
                 size_t rowG, int colB, int tid) {
    #pragma unroll
    for (int i = 0; i < 2; i++) {
        int f = tid + i * 256;
        int r = f >> 3, c = (f & 7) * 8;
        cp_async16(&sb[AKH + r * KSTR + c], gh + (rowG + r) * EDIM + colB + c);
        cp_async16(&sb[AKL + r * KSTR + c], gl + (rowG + r) * EDIM + colB + c);
    }
}
__device__ __forceinline__
void attn_load_v(const bf16* gh, bf16* sb, size_t rowG, int colB, int tid) {
    #pragma unroll
    for (int i = 0; i < 2; i++) {
        int f = tid + i * 256;
        int r = f >> 3, c = (f & 7) * 8;
        cp_async16(&sb[AVH + r * KSTR + c], gh + (rowG + r) * EDIM + colB + c);
    }
}

__global__ __launch_bounds__(256, 2)
void attn_tc_kernel(const bf16* __restrict__ qh, const bf16* __restrict__ ql,
                    const bf16* __restrict__ kh, const bf16* __restrict__ kl,
                    const bf16* __restrict__ vh,
                    const int* __restrict__ mask,
                    bf16* __restrict__ oh, bf16* __restrict__ ol) {
    extern __shared__ char smraw[];
    bf16* sb = (bf16*)smraw;
    float* Sf = (float*)(smraw + SF_OFF);

    int tid = threadIdx.x;
    int wid = tid >> 5;
    int wr = (wid & 3) * 32;
    int wc = (wid >> 2) * 32;
    int b  = blockIdx.y >> 3;
    int hh = blockIdx.y & 7;
    int q0 = blockIdx.x * QT;
    int colB = hh * HD;
    size_t qrow = (size_t)(b * SEQ + q0);
    size_t krow = (size_t)(b * SEQ);

    {
        bf162 sc = __float2bfloat162_rn(0.125f);
        #pragma unroll
        for (int i = 0; i < 4; i++) {
            int f = tid + i * 256;
            int r = f >> 3, c = (f & 7) * 8;
            uint4 uh = *(const uint4*)(qh + (qrow + r) * EDIM + colB + c);
            uint4 ulo = *(const uint4*)(ql + (qrow + r) * EDIM + colB + c);
            bf162* ph = (bf162*)&uh;
            bf162* pl = (bf162*)&ulo;
            #pragma unroll
            for (int j = 0; j < 4; j++) { ph[j] = __hmul2(ph[j], sc); pl[j] = __hmul2(pl[j], sc); }
            *(uint4*)&sb[AQH + r * KSTR + c] = uh;
            *(uint4*)&sb[AQL + r * KSTR + c] = ulo;
        }
    }

    int rr = tid >> 1;
    int pp = tid & 1;
    float o_acc[32];
    #pragma unroll
    for (int i = 0; i < 32; i++) o_acc[i] = 0.f;
    float mrun = -1e30f, lrun = 0.f;

    attn_load_k(kh, kl, sb, krow, colB, tid);
    attn_load_v(vh, sb, krow, colB, tid);
    cp_commit();

    for (int kb = 0; kb < SEQ / 64; kb++) {
        cp_wait<0>();
        __syncthreads();

        // S = Q @ K^T (128x64x64), bf16x3
        {
            wmma::fragment<wmma::matrix_a, 16, 16, 16, bf16, wmma::row_major> qa_h[2], qa_l[2];
            wmma::fragment<wmma::matrix_b, 16, 16, 16, bf16, wmma::col_major> kb_h[2], kb_l[2];
            wmma::fragment<wmma::accumulator, 16, 16, 16, float> sacc[2][2];
            #pragma unroll
            for (int i = 0; i < 2; i++)
                #pragma unroll
                for (int j = 0; j < 2; j++)
                    wmma::fill_fragment(sacc[i][j], 0.f);
            #pragma unroll
            for (int kk = 0; kk < 4; kk++) {
                #pragma unroll
                for (int i = 0; i < 2; i++) {
                    wmma::load_matrix_sync(qa_h[i], &sb[AQH + (wr + i * 16) * KSTR + kk * 16], KSTR);
                    wmma::load_matrix_sync(qa_l[i], &sb[AQL + (wr + i * 16) * KSTR + kk * 16], KSTR);
                }
                #pragma unroll
                for (int j = 0; j < 2; j++) {
                    wmma::load_matrix_sync(kb_h[j], &sb[AKH + (wc + j * 16) * KSTR + kk * 16], KSTR);
                    wmma::load_matrix_sync(kb_l[j], &sb[AKL + (wc + j * 16) * KSTR + kk * 16], KSTR);
                }
                #pragma unroll
                for (int i = 0; i < 2; i++)
                    #pragma unroll
                    for (int j = 0; j < 2; j++) {
                        wmma::mma_sync(sacc[i][j], qa_h[i], kb_h[j], sacc[i][j]);
                        wmma::mma_sync(sacc[i][j], qa_h[i], kb_l[j], sacc[i][j]);
                        wmma::mma_sync(sacc[i][j], qa_l[i], kb_h[j], sacc[i][j]);
                    }
            }
            #pragma unroll
            for (int i = 0; i < 2; i++)
                #pragma unroll
                for (int j = 0; j < 2; j++)
                    wmma::store_matrix_sync(&Sf[(wr + i * 16) * SSTR + wc + j * 16],
                                            sacc[i][j], SSTR, wmma::mem_row_major);
        }
        __syncthreads();

        if (kb + 1 < SEQ / 64)
            attn_load_k(kh, kl, sb, krow + (kb + 1) * 64, colB, tid);
        cp_commit();

        // softmax: 2 threads/row; P stored hi-only
        {
            const float* srow = &Sf[rr * SSTR + pp * 32];
            const int4* mrow = (const int4*)(mask + b * SEQ + kb * 64 + pp * 32);
            float s[32];
            #pragma unroll
            for (int i = 0; i < 8; i++) {
                float4 sv = *(const float4*)(srow + i * 4);
                int4 mk = mrow[i];
                s[4 * i + 0] = mk.x ? sv.x : -1e20f;
                s[4 * i + 1] = mk.y ? sv.y : -1e20f;
                s[4 * i + 2] = mk.z ? sv.z : -1e20f;
                s[4 * i + 3] = mk.w ? sv.w : -1e20f;
            }
            __syncwarp();
            float mloc = s[0];
            #pragma unroll
            for (int i = 1; i < 32; i++) mloc = fmaxf(mloc, s[i]);
            mloc = fmaxf(mloc, __shfl_xor_sync(0xffffffffu, mloc, 1));
            float mnew = fmaxf(mrun, mloc);
            float corr = __expf(mrun - mnew);
            mrun = mnew;
            float psum = 0.f;
            bf162* ph = (bf162*)&sb[PH_OFF + rr * PSTR + pp * 32];
            #pragma unroll
            for (int i = 0; i < 16; i++) {
                float p0 = __expf(s[2 * i] - mnew);
                float p1 = __expf(s[2 * i + 1] - mnew);
                psum += p0 + p1;
                ph[i] = bf162(__float2bfloat16(p0), __float2bfloat16(p1));
            }
            psum += __shfl_xor_sync(0xffffffffu, psum, 1);
            lrun = lrun * corr + psum;
            #pragma unroll
            for (int i = 0; i < 32; i++) o_acc[i] *= corr;
        }
        __syncthreads();

        // Opart = Ph @ Vh (single term)
        {
            wmma::fragment<wmma::matrix_a, 16, 16, 16, bf16, wmma::row_major> pa_h[2];
            wmma::fragment<wmma::matrix_b, 16, 16, 16, bf16, wmma::row_major> vb_h[2];
            wmma::fragment<wmma::accumulator, 16, 16, 16, float> oacc[2][2];
            #pragma unroll
            for (int i = 0; i < 2; i++)
                #pragma unroll
                for (int j = 0; j < 2; j++)
                    wmma::fill_fragment(oacc[i][j], 0.f);
            #pragma unroll
            for (int kk = 0; kk < 4; kk++) {
                #pragma unroll
                for (int i = 0; i < 2; i++)
                    wmma::load_matrix_sync(pa_h[i], &sb[PH_OFF + (wr + i * 16) * PSTR + kk * 16], PSTR);
                #pragma unroll
                for (int j = 0; j < 2; j++)
                    wmma::load_matrix_sync(vb_h[j], &sb[AVH + (kk * 16) * KSTR + wc + j * 16], KSTR);
                #pragma unroll
                for (int i = 0; i < 2; i++)
                    #pragma unroll
                    for (int j = 0; j < 2; j++)
                        wmma::mma_sync(oacc[i][j], pa_h[i], vb_h[j], oacc[i][j]);
            }
            __syncthreads();
            #pragma unroll
            for (int i = 0; i < 2; i++)
                #pragma unroll
                for (int j = 0; j < 2; j++)
                    wmma::store_matrix_sync(&Sf[(wr + i * 16) * SSTR + wc + j * 16],
                                            oacc[i][j], SSTR, wmma::mem_row_major);
        }
        __syncthreads();

        if (kb + 1 < SEQ / 64)
            attn_load_v(vh, sb, krow + (kb + 1) * 64, colB, tid);
        cp_commit();

        {
            const float* orow = &Sf[rr * SSTR + pp * 32];
            #pragma unroll
            for (int i = 0; i < 8; i++) {
                float4 op = *(const float4*)(orow + i * 4);
                o_acc[4 * i + 0] += op.x;
                o_acc[4 * i + 1] += op.y;
                o_acc[4 * i + 2] += op.z;
                o_acc[4 * i + 3] += op.w;
            }
        }
    }

    float inv = 1.f / lrun;
    size_t obase = (qrow + rr) * EDIM + colB + pp * 32;
    #pragma unroll
    for (int i = 0; i < 16; i++) {
        float v0 = o_acc[2 * i] * inv;
        float v1 = o_acc[2 * i + 1] * inv;
        bf16 h0, l0, h1, l1;
        split1(v0, h0, l0); split1(v1, h1, l1);
        *(bf162*)(oh + obase + 2 * i) = bf162(h0, h1);
        *(bf162*)(ol + obase + 2 * i) = bf162(l0, l1);
    }
}

// ---------------- LayerNorm on pre-summed input (fp32 + optional split) --
template <bool SPLIT>
__global__ __launch_bounds__(128)
void ln_kernel(const float* __restrict__ A,
               const float* __restrict__ g, const float* __restrict__ be,
               float* __restrict__ out, bf16* __restrict__ ohi, bf16* __restrict__ olo) {
    __shared__ float red[4];
    int n = blockIdx.x;
    int t = threadIdx.x;
    float4 a = ((const float4*)(A + (size_t)n * EDIM))[t];
    float v[4] = {a.x, a.y, a.z, a.w};

    float s = v[0] + v[1] + v[2] + v[3];
    #pragma unroll
    for (int o = 16; o; o >>= 1) s += __shfl_xor_sync(0xffffffffu, s, o);
    if ((t & 31) == 0) red[t >> 5] = s;
    __syncthreads();
    float mu = (red[0] + red[1] + red[2] + red[3]) * (1.f / EDIM);
    __syncthreads();

    v[0] -= mu; v[1] -= mu; v[2] -= mu; v[3] -= mu;
    float sq = v[0] * v[0] + v[1] * v[1] + v[2] * v[2] + v[3] * v[3];
    #pragma unroll
    for (int o = 16; o; o >>= 1) sq += __shfl_xor_sync(0xffffffffu, sq, o);
    if ((t & 31) == 0) red[t >> 5] = sq;
    __syncthreads();
    float var = (red[0] + red[1] + red[2] + red[3]) * (1.f / EDIM);
    float rs = rsqrtf(var + 1e-6f);

    float4 gg = ((const float4*)g)[t];
    float4 bb = ((const float4*)be)[t];
    float o0 = v[0] * rs * gg.x + bb.x;
    float o1 = v[1] * rs * gg.y + bb.y;
    float o2 = v[2] * rs * gg.z + bb.z;
    float o3 = v[3] * rs * gg.w + bb.w;
    float4 o = {o0, o1, o2, o3};
    ((float4*)(out + (size_t)n * EDIM))[t] = o;
    if (SPLIT) {
        bf16 h0, l0, h1, l1, h2, l2, h3, l3;
        split1(o0, h0, l0); split1(o1, h1, l1);
        split1(o2, h2, l2); split1(o3, h3, l3);
        size_t off = (size_t)n * EDIM + t * 4;
        *(bf162*)(ohi + off)     = bf162(h0, h1);
        *(bf162*)(ohi + off + 2) = bf162(h2, h3);
        *(bf162*)(olo + off)     = bf162(l0, l1);
        *(bf162*)(olo + off + 2) = bf162(l2, l3);
    }
}

// ---------------- launcher ----------------
extern "C" void kernel_launch(void* const* d_in, const int* in_sizes, int n_in,
                              void* d_out, int out_size) {
    const int*   x    = (const int*)  d_in[0];
    const int*   mask = (const int*)  d_in[1];
    const float* emb  = (const float*)d_in[2];
    const float* pos  = (const float*)d_in[3];
    const float* Wq   = (const float*)d_in[4];
    const float* bq   = (const float*)d_in[5];
    const float* Wk   = (const float*)d_in[6];
    const float* bk   = (const float*)d_in[7];
    const float* Wv   = (const float*)d_in[8];
    const float* bv   = (const float*)d_in[9];
    const float* Wo   = (const float*)d_in[10];
    const float* bo   = (const float*)d_in[11];
    const float* g1   = (const float*)d_in[12];
    const float* be1  = (const float*)d_in[13];
    const float* g2   = (const float*)d_in[14];
    const float* be2  = (const float*)d_in[15];
    const float* W1   = (const float*)d_in[16];
    const float* bf1  = (const float*)d_in[17];
    const float* W2   = (const float*)d_in[18];
    const float* bf2  = (const float*)d_in[19];
    float* outp = (float*)d_out;

    float *h32, *p32;
    bf16 *hh, *hl, *qh, *ql, *kh, *kl, *vh, *vl, *ah, *al, *fh, *fl;
    bf16 *wqh, *wql, *wkh, *wkl, *wvh, *wvl, *woh, *wol, *w1h, *w1l, *w2h, *w2l;
    cudaGetSymbolAddress((void**)&h32, g_h32);
    cudaGetSymbolAddress((void**)&p32, g_p32);
    cudaGetSymbolAddress((void**)&hh, g_hh); cudaGetSymbolAddress((void**)&hl, g_hl);
    cudaGetSymbolAddress((void**)&qh, g_qh); cudaGetSymbolAddress((void**)&ql, g_ql);
    cudaGetSymbolAddress((void**)&kh, g_kh); cudaGetSymbolAddress((void**)&kl, g_kl);
    cudaGetSymbolAddress((void**)&vh, g_vh); cudaGetSymbolAddress((void**)&vl, g_vl);
    cudaGetSymbolAddress((void**)&ah, g_ah); cudaGetSymbolAddress((void**)&al, g_al);
    cudaGetSymbolAddress((void**)&fh, g_fh); cudaGetSymbolAddress((void**)&fl, g_fl);
    cudaGetSymbolAddress((void**)&wqh, g_wqh); cudaGetSymbolAddress((void**)&wql, g_wql);
    cudaGetSymbolAddress((void**)&wkh, g_wkh); cudaGetSymbolAddress((void**)&wkl, g_wkl);
    cudaGetSymbolAddress((void**)&wvh, g_wvh); cudaGetSymbolAddress((void**)&wvl, g_wvl);
    cudaGetSymbolAddress((void**)&woh, g_woh); cudaGetSymbolAddress((void**)&wol, g_wol);
    cudaGetSymbolAddress((void**)&w1h, g_w1h); cudaGetSymbolAddress((void**)&w1l, g_w1l);
    cudaGetSymbolAddress((void**)&w2h, g_w2h); cudaGetSymbolAddress((void**)&w2l, g_w2l);

    cudaFuncSetAttribute(attn_tc_kernel, cudaFuncAttributeMaxDynamicSharedMemorySize, ATTN_SMEM);
    cudaFuncSetAttribute(gemm_tc_kernel<1>, cudaFuncAttributeMaxDynamicSharedMemorySize, GEMM_SMEM);
    cudaFuncSetAttribute(gemm_tc_kernel<2>, cudaFuncAttributeMaxDynamicSharedMemorySize, GEMM_SMEM);
    cudaFuncSetAttribute(gemm_tc_kernel<3>, cudaFuncAttributeMaxDynamicSharedMemorySize, GEMM_SMEM);
    cudaFuncSetAttribute(gemm_qkv_kernel, cudaFuncAttributeMaxDynamicSharedMemorySize, GEMM_SMEM);

    split_kernel<<<NLAYER * EDIM * EDIM / 1024, 256>>>(Wq, wqh, wql);
    split_kernel<<<NLAYER * EDIM * EDIM / 1024, 256>>>(Wk, wkh, wkl);
    split_kernel<<<NLAYER * EDIM * EDIM / 1024, 256>>>(Wv, wvh, wvl);
    split_kernel<<<NLAYER * EDIM * EDIM / 1024, 256>>>(Wo, woh, wol);
    split_kernel<<<NLAYER * EDIM * FFDIM / 1024, 256>>>(W1, w1h, w1l);
    split_kernel<<<NLAYER * FFDIM * EDIM / 1024, 256>>>(W2, w2h, w2l);

    embed_kernel<<<(NTOK * EDIM) / 256, 256>>>(x, emb, pos, h32, hh, hl);

    dim3 gE(EDIM / BN, NTOK / BM);
    dim3 gQKV(EDIM / BN, NTOK / BM, 3);
    dim3 gF(FFDIM / BN, NTOK / BM);

    for (int l = 0; l < NLAYER; l++) {
        size_t wo_off = (size_t)l * EDIM * EDIM;
        size_t w1_off = (size_t)l * EDIM * FFDIM;
        size_t w2_off = (size_t)l * FFDIM * EDIM;

        gemm_qkv_kernel<<<gQKV, 128, GEMM_SMEM>>>(
            hh, hl,
            wqh + wo_off, wql + wo_off, wkh + wo_off, wkl + wo_off,
            wvh + wo_off, wvl + wo_off,
            bq + l * EDIM, bk + l * EDIM, bv + l * EDIM,
            qh, ql, kh, kl, vh, vl);

        attn_tc_kernel<<<dim3(SEQ / QT, NB * HEADS), 256, ATTN_SMEM>>>(
            qh, ql, kh, kl, vh, mask, ah, al);

        // p32 = attn @ Wo + bo + h32  (residual fused)
        gemm_tc_kernel<3><<<gE, 128, GEMM_SMEM>>>(
            ah, al, woh + wo_off, wol + wo_off, bo + l * EDIM, h32, p32, nullptr, nullptr,
            EDIM, EDIM);
        ln_kernel<true><<<NTOK, 128>>>(p32, g1 + l * EDIM, be1 + l * EDIM, h32, hh, hl);

        gemm_tc_kernel<2><<<gF, 128, GEMM_SMEM>>>(
            hh, hl, w1h + w1_off, w1l + w1_off, bf1 + l * FFDIM, nullptr, nullptr, fh, fl,
            EDIM, FFDIM);
        // p32 = ffn @ W2 + bf2 + h32  (residual fused)
        gemm_tc_kernel<3><<<gE, 128, GEMM_SMEM>>>(
            fh, fl, w2h + w2_off, w2l + w2_off, bf2 + l * EDIM, h32, p32, nullptr, nullptr,
            FFDIM, EDIM);

        if (l == NLAYER - 1)
            ln_kernel<false><<<NTOK, 128>>>(p32, g2 + l * EDIM, be2 + l * EDIM,
                                            outp, nullptr, nullptr);
        else
            ln_kernel<true><<<NTOK, 128>>>(p32, g2 + l * EDIM, be2 + l * EDIM,
                                           h32, hh, hl);
    }
}